// round 3
// baseline (speedup 1.0000x reference)
#include <cuda_runtime.h>
#include <cuda_bf16.h>
#include <math.h>

// ---------------------------------------------------------------------------
// KroneckerMoE v3:
//   K1: router logits via bf16 mma.sync m16n8k16 (approx, selection-only)
//   K2: fused: approx top-6 -> exact fp32 re-rank -> softmax ->
//       expert bilinear (shared-X stage1, f32x2 FFMA2) -> scale+bias
// ---------------------------------------------------------------------------

#define ROUTER_K   1024
#define MAX_TOKENS 16384
#define MAX_E      256

__device__ float g_logits[(size_t)MAX_TOKENS * MAX_E];

// ======================= Kernel 1: bf16 mma router =========================
#define R_BM 128
#define R_BN 64
#define R_BK 32
#define XPAD 20   // uint32 words per row (16 data + 4 pad) -> conflict-free frags

__device__ __forceinline__ void mma_bf16(float d[4], const unsigned a[4], const unsigned b[2]) {
    asm volatile(
        "mma.sync.aligned.m16n8k16.row.col.f32.bf16.bf16.f32 "
        "{%0,%1,%2,%3}, {%4,%5,%6,%7}, {%8,%9}, {%0,%1,%2,%3};\n"
        : "+f"(d[0]), "+f"(d[1]), "+f"(d[2]), "+f"(d[3])
        : "r"(a[0]), "r"(a[1]), "r"(a[2]), "r"(a[3]), "r"(b[0]), "r"(b[1]));
}

__device__ __forceinline__ unsigned pack_bf16(float lo, float hi) {
    __nv_bfloat162 h = __float22bfloat162_rn(make_float2(lo, hi));
    return *(unsigned*)&h;
}

__global__ __launch_bounds__(256)
void router_mma_kernel(const float* __restrict__ X, const float* __restrict__ W,
                       int M, int E) {
    __shared__ unsigned Xs[R_BM][XPAD];
    __shared__ unsigned Ws[R_BN][XPAD];
    const int bm   = blockIdx.x * R_BM;
    const int bn   = blockIdx.y * R_BN;
    const int tid  = threadIdx.x;
    const int wid  = tid >> 5;
    const int lane = tid & 31;
    const int wm   = wid & 3;
    const int wn   = wid >> 2;
    const int g    = lane >> 2;
    const int t    = lane & 3;

    float d[2][4][4];
    #pragma unroll
    for (int mt = 0; mt < 2; mt++)
        #pragma unroll
        for (int nt = 0; nt < 4; nt++)
            #pragma unroll
            for (int r = 0; r < 4; r++) d[mt][nt][r] = 0.f;

    const int K4 = ROUTER_K / 4;
    for (int k0 = 0; k0 < ROUTER_K; k0 += R_BK) {
        // X tile 128x32 floats -> bf16: 1024 ids, 4 per thread
        #pragma unroll
        for (int l = 0; l < 4; l++) {
            int id = tid + l * 256;
            int r  = id >> 3;
            int q  = id & 7;
            float4 v = ((const float4*)X)[(size_t)(bm + r) * K4 + (k0 >> 2) + q];
            uint2 u = make_uint2(pack_bf16(v.x, v.y), pack_bf16(v.z, v.w));
            *(uint2*)&Xs[r][q * 2] = u;
        }
        // W tile 64x32 floats -> bf16: 512 ids, 2 per thread
        #pragma unroll
        for (int l = 0; l < 2; l++) {
            int id = tid + l * 256;
            int r  = id >> 3;
            int q  = id & 7;
            float4 v = ((const float4*)W)[(size_t)(bn + r) * K4 + (k0 >> 2) + q];
            uint2 u = make_uint2(pack_bf16(v.x, v.y), pack_bf16(v.z, v.w));
            *(uint2*)&Ws[r][q * 2] = u;
        }
        __syncthreads();
        #pragma unroll
        for (int ks = 0; ks < 2; ks++) {
            const int kw = ks * 8 + t;
            unsigned a[2][4];
            #pragma unroll
            for (int mt = 0; mt < 2; mt++) {
                const int rb = wm * 32 + mt * 16;
                a[mt][0] = Xs[rb + g    ][kw];
                a[mt][1] = Xs[rb + g + 8][kw];
                a[mt][2] = Xs[rb + g    ][kw + 4];
                a[mt][3] = Xs[rb + g + 8][kw + 4];
            }
            unsigned b[4][2];
            #pragma unroll
            for (int nt = 0; nt < 4; nt++) {
                const int cb = wn * 32 + nt * 8;
                b[nt][0] = Ws[cb + g][kw];
                b[nt][1] = Ws[cb + g][kw + 4];
            }
            #pragma unroll
            for (int mt = 0; mt < 2; mt++)
                #pragma unroll
                for (int nt = 0; nt < 4; nt++)
                    mma_bf16(d[mt][nt], a[mt], b[nt]);
        }
        __syncthreads();
    }
    #pragma unroll
    for (int mt = 0; mt < 2; mt++) {
        #pragma unroll
        for (int nt = 0; nt < 4; nt++) {
            const int row = bm + wm * 32 + mt * 16 + g;
            const int col = bn + wn * 32 + nt * 8 + 2 * t;
            *(float2*)(g_logits + (size_t)row * E + col)       = make_float2(d[mt][nt][0], d[mt][nt][1]);
            *(float2*)(g_logits + (size_t)(row + 8) * E + col) = make_float2(d[mt][nt][2], d[mt][nt][3]);
        }
    }
}

// ================= Kernel 2: fused rerank + expert (f32x2) =================
#define TPB_TOK 4
#define NCAND   6

__device__ __forceinline__ bool pair_better(float v, int i, float w, int j) {
    return (v > w) || (v == w && i < j);
}
__device__ __forceinline__ unsigned long long pack2(float lo, float hi) {
    unsigned long long r;
    asm("mov.b64 %0, {%1, %2};" : "=l"(r) : "r"(__float_as_uint(lo)), "r"(__float_as_uint(hi)));
    return r;
}
__device__ __forceinline__ void unpack2(unsigned long long v, float& lo, float& hi) {
    unsigned a, b;
    asm("mov.b64 {%0, %1}, %2;" : "=r"(a), "=r"(b) : "l"(v));
    lo = __uint_as_float(a); hi = __uint_as_float(b);
}
__device__ __forceinline__ void ffma2(unsigned long long& d, unsigned long long a, unsigned long long b) {
    asm("fma.rn.f32x2 %0, %1, %2, %0;" : "+l"(d) : "l"(a), "l"(b));
}

__global__ __launch_bounds__(128)
void expert_fused_kernel(const float* __restrict__ x,
                         const float* __restrict__ RW,
                         const float* __restrict__ Ae,
                         const float* __restrict__ Be,
                         const float* __restrict__ scale,
                         const float* __restrict__ bias,
                         float* __restrict__ out, int M, int E) {
    __shared__ float XsAll[TPB_TOK][1056];        // x row; reused for output staging
    __shared__ float BtAll[TPB_TOK][32 * 36];     // B transposed [j][p], pad 36
    const int wid  = threadIdx.x >> 5;
    const int lane = threadIdx.x & 31;
    const int n    = blockIdx.x * TPB_TOK + wid;
    if (n >= M) return;
    float* xs = XsAll[wid];
    float* bt = BtAll[wid];

    // ---- load x row (coalesced); keep this lane's 32-float chunk in regs ----
    float4 xr4[8];
    {
        const float4* xg = (const float4*)(x + (size_t)n * 1024);
        float4* xs4 = (float4*)xs;
        #pragma unroll
        for (int i = 0; i < 8; i++) {
            float4 v = xg[i * 32 + lane];
            xs4[i * 32 + lane] = v;
        }
        const float4* xg2 = (const float4*)(x + (size_t)n * 1024 + lane * 32);
        #pragma unroll
        for (int q = 0; q < 8; q++) xr4[q] = xg2[q];   // L1-hot re-read
    }
    __syncwarp();

    // ---- approx top-6 from bf16 logits ----
    const int NJ = E >> 5;
    float lv[8];
    const float* lrow = g_logits + (size_t)n * E;
    #pragma unroll
    for (int j = 0; j < 8; j++) lv[j] = (j < NJ) ? lrow[lane + 32 * j] : -3.4e38f;

    int cand[NCAND];
    #pragma unroll
    for (int it = 0; it < NCAND; it++) {
        float bv = -3.4e38f; int be = 0x7fffffff;
        #pragma unroll
        for (int j = 0; j < 8; j++) {
            int e = lane + 32 * j;
            if (j < NJ && pair_better(lv[j], e, bv, be)) { bv = lv[j]; be = e; }
        }
        #pragma unroll
        for (int off = 16; off > 0; off >>= 1) {
            float ov = __shfl_xor_sync(0xffffffffu, bv, off);
            int   oe = __shfl_xor_sync(0xffffffffu, be, off);
            if (pair_better(ov, oe, bv, be)) { bv = ov; be = oe; }
        }
        cand[it] = be;
        if ((be & 31) == lane) lv[be >> 5] = -3.4e38f;
    }

    // ---- exact fp32 dots for the candidates (vectorized chunks) ----
    float s[NCAND];
    #pragma unroll
    for (int c = 0; c < NCAND; c++) {
        const float4* wr = (const float4*)(RW + (size_t)cand[c] * 1024 + lane * 32);
        float acc = 0.f;
        #pragma unroll
        for (int q = 0; q < 8; q++) {
            float4 wv = wr[q];
            acc += xr4[q].x * wv.x + xr4[q].y * wv.y + xr4[q].z * wv.z + xr4[q].w * wv.w;
        }
        s[c] = acc;
    }
    #pragma unroll
    for (int off = 16; off > 0; off >>= 1) {
        #pragma unroll
        for (int c = 0; c < NCAND; c++) s[c] += __shfl_xor_sync(0xffffffffu, s[c], off);
    }

    // ---- exact top-2 of the candidates + softmax ----
    float v0 = s[0]; int c0 = 0;
    #pragma unroll
    for (int c = 1; c < NCAND; c++)
        if (pair_better(s[c], cand[c], v0, cand[c0])) { v0 = s[c]; c0 = c; }
    float v1 = -3.4e38f; int c1 = -1;
    #pragma unroll
    for (int c = 0; c < NCAND; c++)
        if (c != c0 && (c1 < 0 || pair_better(s[c], cand[c], v1, cand[c1]))) { v1 = s[c]; c1 = c; }
    const int e0 = cand[c0], e1 = cand[c1];
    const float tt = expf(v1 - v0);
    const float w0 = 1.f / (1.f + tt);
    const float w1 = tt * w0;

    // ---- stage 1 (shared X pass): T_k[j] = sum_i (w_k*A_k[lane][i]) * X[i][j]
    unsigned long long T0[16], T1[16];
    #pragma unroll
    for (int q = 0; q < 16; q++) { T0[q] = 0ull; T1[q] = 0ull; }

    const float4* ag0 = (const float4*)(Ae + (size_t)e0 * 1024 + lane * 32);
    const float4* ag1 = (const float4*)(Ae + (size_t)e1 * 1024 + lane * 32);
    #pragma unroll
    for (int h = 0; h < 2; h++) {
        float a0h[16], a1h[16];
        #pragma unroll
        for (int q = 0; q < 4; q++) {
            float4 v0f = ag0[h * 4 + q];
            a0h[4*q+0] = v0f.x * w0; a0h[4*q+1] = v0f.y * w0;
            a0h[4*q+2] = v0f.z * w0; a0h[4*q+3] = v0f.w * w0;
            float4 v1f = ag1[h * 4 + q];
            a1h[4*q+0] = v1f.x * w1; a1h[4*q+1] = v1f.y * w1;
            a1h[4*q+2] = v1f.z * w1; a1h[4*q+3] = v1f.w * w1;
        }
        #pragma unroll
        for (int ii = 0; ii < 16; ii++) {
            const int i = h * 16 + ii;
            unsigned long long p0 = pack2(a0h[ii], a0h[ii]);
            unsigned long long p1 = pack2(a1h[ii], a1h[ii]);
            const ulonglong2* xr = (const ulonglong2*)(xs + i * 32);
            #pragma unroll
            for (int q = 0; q < 8; q++) {
                ulonglong2 xx = xr[q];
                ffma2(T0[2*q],   p0, xx.x);
                ffma2(T0[2*q+1], p0, xx.y);
                ffma2(T1[2*q],   p1, xx.x);
                ffma2(T1[2*q+1], p1, xx.y);
            }
        }
    }

    // ---- stage 2: y[p] += sum_j T_k[j] * B_k[p][j], experts sequential ----
    unsigned long long y2[16];
    #pragma unroll
    for (int p = 0; p < 16; p++) y2[p] = 0ull;

    #pragma unroll
    for (int kk = 0; kk < 2; kk++) {
        const int e = kk ? e1 : e0;
        const unsigned long long* T = kk ? T1 : T0;
        {   // B[e] -> smem transposed: bt[j*36 + p]
            const float4* bg = (const float4*)(Be + (size_t)e * 1024);
            #pragma unroll
            for (int i = 0; i < 8; i++) {
                int idx = i * 32 + lane;
                int p   = idx >> 3;
                int j4  = idx & 7;
                float4 v = bg[idx];
                bt[(4 * j4 + 0) * 36 + p] = v.x;
                bt[(4 * j4 + 1) * 36 + p] = v.y;
                bt[(4 * j4 + 2) * 36 + p] = v.z;
                bt[(4 * j4 + 3) * 36 + p] = v.w;
            }
        }
        __syncwarp();
        #pragma unroll
        for (int j2 = 0; j2 < 16; j2++) {
            float t0, t1; unpack2(T[j2], t0, t1);
            unsigned long long tb0 = pack2(t0, t0);
            unsigned long long tb1 = pack2(t1, t1);
            const ulonglong2* br0 = (const ulonglong2*)(bt + (2*j2)   * 36);
            const ulonglong2* br1 = (const ulonglong2*)(bt + (2*j2+1) * 36);
            #pragma unroll
            for (int q = 0; q < 8; q++) {
                ulonglong2 bb = br0[q];
                ffma2(y2[2*q],   tb0, bb.x);
                ffma2(y2[2*q+1], tb0, bb.y);
            }
            #pragma unroll
            for (int q = 0; q < 8; q++) {
                ulonglong2 bb = br1[q];
                ffma2(y2[2*q],   tb1, bb.x);
                ffma2(y2[2*q+1], tb1, bb.y);
            }
        }
        __syncwarp();   // before next expert overwrites bt
    }

    // ---- epilogue: stage through smem, coalesced write with scale+bias ----
    #pragma unroll
    for (int p2 = 0; p2 < 16; p2++) {
        float lo, hi; unpack2(y2[p2], lo, hi);
        xs[lane * 33 + 2 * p2]     = lo;
        xs[lane * 33 + 2 * p2 + 1] = hi;
    }
    __syncwarp();
    const float sc = *scale;
    float* og = out + (size_t)n * 1024;
    #pragma unroll
    for (int i = 0; i < 32; i++) {
        int q = i * 32 + lane;
        og[q] = xs[i * 33 + lane] * sc + bias[q];
    }
}

// ================================ launch ===================================
extern "C" void kernel_launch(void* const* d_in, const int* in_sizes, int n_in,
                              void* d_out, int out_size) {
    const float* x  = (const float*)d_in[0];
    const float* rw = (const float*)d_in[1];
    const float* Ae = (const float*)d_in[2];
    const float* Be = (const float*)d_in[3];
    const float* sc = (const float*)d_in[4];
    const float* bi = (const float*)d_in[5];
    float* out = (float*)d_out;

    const int M = in_sizes[0] / ROUTER_K;   // 16384
    const int E = in_sizes[1] / ROUTER_K;   // 256

    dim3 g1(M / R_BM, E / R_BN);
    router_mma_kernel<<<g1, 256>>>(x, rw, M, E);

    expert_fused_kernel<<<(M + TPB_TOK - 1) / TPB_TOK, 128>>>(
        x, rw, Ae, Be, sc, bi, out, M, E);
}

// round 4
// speedup vs baseline: 1.2857x; 1.2857x over previous
#include <cuda_runtime.h>
#include <cuda_bf16.h>
#include <math.h>

// ---------------------------------------------------------------------------
// KroneckerMoE v4:
//   K1: router logits via bf16 mma.sync m16n8k16 (selection-only, R3-proven)
//   K2: fused: approx top-6 -> exact fp32 re-rank -> softmax ->
//       expert bilinear on TENSOR CORES via bf16 3-term split (err ~1e-5)
// ---------------------------------------------------------------------------

#define ROUTER_K   1024
#define MAX_TOKENS 16384
#define MAX_E      256

__device__ float g_logits[(size_t)MAX_TOKENS * MAX_E];

// ======================= shared mma helper =========================
__device__ __forceinline__ void mma_bf16(float d[4], const unsigned a[4], const unsigned b[2]) {
    asm volatile(
        "mma.sync.aligned.m16n8k16.row.col.f32.bf16.bf16.f32 "
        "{%0,%1,%2,%3}, {%4,%5,%6,%7}, {%8,%9}, {%0,%1,%2,%3};\n"
        : "+f"(d[0]), "+f"(d[1]), "+f"(d[2]), "+f"(d[3])
        : "r"(a[0]), "r"(a[1]), "r"(a[2]), "r"(a[3]), "r"(b[0]), "r"(b[1]));
}

__device__ __forceinline__ unsigned pack_bf16(float lo, float hi) {
    __nv_bfloat162 h = __float22bfloat162_rn(make_float2(lo, hi));
    return *(unsigned*)&h;
}

// single-instruction dual convert: d.lo = bf16(lo), d.hi = bf16(hi)
__device__ __forceinline__ unsigned cvt2_bf16(float hi, float lo) {
    unsigned d;
    asm("cvt.rn.bf16x2.f32 %0, %1, %2;" : "=r"(d) : "f"(hi), "f"(lo));
    return d;
}
__device__ __forceinline__ float bf16lo_f(unsigned u) { return __uint_as_float(u << 16); }
__device__ __forceinline__ float bf16hi_f(unsigned u) { return __uint_as_float(u & 0xffff0000u); }
// split (e0,e1) into packed bf16 hi + packed bf16 residual
__device__ __forceinline__ void split_pair(float e0, float e1, unsigned& h, unsigned& l) {
    h = cvt2_bf16(e1, e0);
    float r0 = e0 - bf16lo_f(h);
    float r1 = e1 - bf16hi_f(h);
    l = cvt2_bf16(r1, r0);
}

// ======================= Kernel 1: bf16 mma router (unchanged) =============
#define R_BM 128
#define R_BN 64
#define R_BK 32
#define XPAD 20

__global__ __launch_bounds__(256)
void router_mma_kernel(const float* __restrict__ X, const float* __restrict__ W,
                       int M, int E) {
    __shared__ unsigned Xs[R_BM][XPAD];
    __shared__ unsigned Ws[R_BN][XPAD];
    const int bm   = blockIdx.x * R_BM;
    const int bn   = blockIdx.y * R_BN;
    const int tid  = threadIdx.x;
    const int wid  = tid >> 5;
    const int lane = tid & 31;
    const int wm   = wid & 3;
    const int wn   = wid >> 2;
    const int g    = lane >> 2;
    const int t    = lane & 3;

    float d[2][4][4];
    #pragma unroll
    for (int mt = 0; mt < 2; mt++)
        #pragma unroll
        for (int nt = 0; nt < 4; nt++)
            #pragma unroll
            for (int r = 0; r < 4; r++) d[mt][nt][r] = 0.f;

    const int K4 = ROUTER_K / 4;
    for (int k0 = 0; k0 < ROUTER_K; k0 += R_BK) {
        #pragma unroll
        for (int l = 0; l < 4; l++) {
            int id = tid + l * 256;
            int r  = id >> 3;
            int q  = id & 7;
            float4 v = ((const float4*)X)[(size_t)(bm + r) * K4 + (k0 >> 2) + q];
            uint2 u = make_uint2(pack_bf16(v.x, v.y), pack_bf16(v.z, v.w));
            *(uint2*)&Xs[r][q * 2] = u;
        }
        #pragma unroll
        for (int l = 0; l < 2; l++) {
            int id = tid + l * 256;
            int r  = id >> 3;
            int q  = id & 7;
            float4 v = ((const float4*)W)[(size_t)(bn + r) * K4 + (k0 >> 2) + q];
            uint2 u = make_uint2(pack_bf16(v.x, v.y), pack_bf16(v.z, v.w));
            *(uint2*)&Ws[r][q * 2] = u;
        }
        __syncthreads();
        #pragma unroll
        for (int ks = 0; ks < 2; ks++) {
            const int kw = ks * 8 + t;
            unsigned a[2][4];
            #pragma unroll
            for (int mt = 0; mt < 2; mt++) {
                const int rb = wm * 32 + mt * 16;
                a[mt][0] = Xs[rb + g    ][kw];
                a[mt][1] = Xs[rb + g + 8][kw];
                a[mt][2] = Xs[rb + g    ][kw + 4];
                a[mt][3] = Xs[rb + g + 8][kw + 4];
            }
            unsigned b[4][2];
            #pragma unroll
            for (int nt = 0; nt < 4; nt++) {
                const int cb = wn * 32 + nt * 8;
                b[nt][0] = Ws[cb + g][kw];
                b[nt][1] = Ws[cb + g][kw + 4];
            }
            #pragma unroll
            for (int mt = 0; mt < 2; mt++)
                #pragma unroll
                for (int nt = 0; nt < 4; nt++)
                    mma_bf16(d[mt][nt], a[mt], b[nt]);
        }
        __syncthreads();
    }
    #pragma unroll
    for (int mt = 0; mt < 2; mt++) {
        #pragma unroll
        for (int nt = 0; nt < 4; nt++) {
            const int row = bm + wm * 32 + mt * 16 + g;
            const int col = bn + wn * 32 + nt * 8 + 2 * t;
            *(float2*)(g_logits + (size_t)row * E + col)       = make_float2(d[mt][nt][0], d[mt][nt][1]);
            *(float2*)(g_logits + (size_t)(row + 8) * E + col) = make_float2(d[mt][nt][2], d[mt][nt][3]);
        }
    }
}

// ============== Kernel 2: fused rerank + tensor-core expert ================
#define TPB_TOK 4
#define NCAND   6
#define XSTRIDE 36   // fp32 words per row of X tile (conflict-friendly, 16B aligned)
#define YSTRIDE 34   // output staging stride (even -> float2 aligned)

__device__ __forceinline__ bool pair_better(float v, int i, float w, int j) {
    return (v > w) || (v == w && i < j);
}

__global__ __launch_bounds__(128)
void expert_fused_kernel(const float* __restrict__ x,
                         const float* __restrict__ RW,
                         const float* __restrict__ Ae,
                         const float* __restrict__ Be,
                         const float* __restrict__ scale,
                         const float* __restrict__ bias,
                         float* __restrict__ out, int M, int E) {
    __shared__ float XsAll[TPB_TOK][32 * XSTRIDE];   // X tile; reused as Y staging
    const int wid  = threadIdx.x >> 5;
    const int lane = threadIdx.x & 31;
    const int n    = blockIdx.x * TPB_TOK + wid;
    if (n >= M) return;
    float* xs = XsAll[wid];
    const int g = lane >> 2;    // 0..7
    const int t = lane & 3;     // 0..3

    // ---- load x row into smem (coalesced) + keep a reg chunk for rerank ----
    float4 xr4[8];
    {
        const float4* xg = (const float4*)(x + (size_t)n * 1024);
        #pragma unroll
        for (int i = 0; i < 8; i++) {
            int idx = i * 32 + lane;          // float4 index 0..255
            int r   = idx >> 3;
            int q   = idx & 7;
            *(float4*)&xs[r * XSTRIDE + q * 4] = xg[idx];
        }
        const float4* xg2 = (const float4*)(x + (size_t)n * 1024 + lane * 32);
        #pragma unroll
        for (int q = 0; q < 8; q++) xr4[q] = xg2[q];
    }
    __syncwarp();

    // ---- approx top-6 from bf16 logits ----
    const int NJ = E >> 5;
    float lv[8];
    const float* lrow = g_logits + (size_t)n * E;
    #pragma unroll
    for (int j = 0; j < 8; j++) lv[j] = (j < NJ) ? lrow[lane + 32 * j] : -3.4e38f;

    int cand[NCAND];
    #pragma unroll
    for (int it = 0; it < NCAND; it++) {
        float bv = -3.4e38f; int be = 0x7fffffff;
        #pragma unroll
        for (int j = 0; j < 8; j++) {
            int e = lane + 32 * j;
            if (j < NJ && pair_better(lv[j], e, bv, be)) { bv = lv[j]; be = e; }
        }
        #pragma unroll
        for (int off = 16; off > 0; off >>= 1) {
            float ov = __shfl_xor_sync(0xffffffffu, bv, off);
            int   oe = __shfl_xor_sync(0xffffffffu, be, off);
            if (pair_better(ov, oe, bv, be)) { bv = ov; be = oe; }
        }
        cand[it] = be;
        if ((be & 31) == lane) lv[be >> 5] = -3.4e38f;
    }

    // ---- exact fp32 dots for candidates ----
    float s[NCAND];
    #pragma unroll
    for (int c = 0; c < NCAND; c++) {
        const float4* wr = (const float4*)(RW + (size_t)cand[c] * 1024 + lane * 32);
        float acc = 0.f;
        #pragma unroll
        for (int q = 0; q < 8; q++) {
            float4 wv = wr[q];
            acc += xr4[q].x * wv.x + xr4[q].y * wv.y + xr4[q].z * wv.z + xr4[q].w * wv.w;
        }
        s[c] = acc;
    }
    #pragma unroll
    for (int off = 16; off > 0; off >>= 1) {
        #pragma unroll
        for (int c = 0; c < NCAND; c++) s[c] += __shfl_xor_sync(0xffffffffu, s[c], off);
    }

    // ---- exact top-2 + softmax ----
    float v0 = s[0]; int c0 = 0;
    #pragma unroll
    for (int c = 1; c < NCAND; c++)
        if (pair_better(s[c], cand[c], v0, cand[c0])) { v0 = s[c]; c0 = c; }
    float v1 = -3.4e38f; int c1 = -1;
    #pragma unroll
    for (int c = 0; c < NCAND; c++)
        if (c != c0 && (c1 < 0 || pair_better(s[c], cand[c], v1, cand[c1]))) { v1 = s[c]; c1 = c; }
    const int e0 = cand[c0], e1 = cand[c1];
    const float tt = expf(v1 - v0);
    const float w0 = 1.f / (1.f + tt);
    const float w1 = tt * w0;

    // ---- build X b-fragments (bf16 hi/lo) once per token ----
    // b-frag for tile (kt,nt): reg[part] packs X[kt*16+2t+8*part][nt*8+g],
    //                                        X[kt*16+2t+8*part+1][nt*8+g]
    unsigned xbh[2][4][2], xbl[2][4][2];
    #pragma unroll
    for (int kt = 0; kt < 2; kt++)
        #pragma unroll
        for (int nt = 0; nt < 4; nt++)
            #pragma unroll
            for (int part = 0; part < 2; part++) {
                int krow = kt * 16 + 2 * t + 8 * part;
                float e0f = xs[krow * XSTRIDE + nt * 8 + g];
                float e1f = xs[(krow + 1) * XSTRIDE + nt * 8 + g];
                split_pair(e0f, e1f, xbh[kt][nt][part], xbl[kt][nt][part]);
            }

    // ---- per-expert: T = A@X (stage A), Y += w * T@B^T (stage B) ----
    float Y[2][4][4];
    #pragma unroll
    for (int mt = 0; mt < 2; mt++)
        #pragma unroll
        for (int nt = 0; nt < 4; nt++)
            #pragma unroll
            for (int r = 0; r < 4; r++) Y[mt][nt][r] = 0.f;

    #pragma unroll
    for (int kk = 0; kk < 2; kk++) {
        const int   e = kk ? e1 : e0;
        const float w = kk ? w1 : w0;

        // --- stage A ---
        float tA[2][4][4];
        #pragma unroll
        for (int mt = 0; mt < 2; mt++)
            #pragma unroll
            for (int nt = 0; nt < 4; nt++)
                #pragma unroll
                for (int r = 0; r < 4; r++) tA[mt][nt][r] = 0.f;

        #pragma unroll
        for (int kt = 0; kt < 2; kt++) {
            unsigned ah[2][4], al[2][4];
            #pragma unroll
            for (int mt = 0; mt < 2; mt++) {
                const float* ap = Ae + (size_t)e * 1024 + (mt * 16 + g) * 32 + kt * 16;
                float2 p0 = *(const float2*)(ap + 2 * t);            // row g,   k 2t..2t+1
                float2 p1 = *(const float2*)(ap + 2 * t + 8);        // row g,   k 2t+8..
                float2 p2 = *(const float2*)(ap + 8 * 32 + 2 * t);   // row g+8, k 2t..
                float2 p3 = *(const float2*)(ap + 8 * 32 + 2 * t + 8);
                split_pair(p0.x, p0.y, ah[mt][0], al[mt][0]);
                split_pair(p2.x, p2.y, ah[mt][1], al[mt][1]);
                split_pair(p1.x, p1.y, ah[mt][2], al[mt][2]);
                split_pair(p3.x, p3.y, ah[mt][3], al[mt][3]);
            }
            #pragma unroll
            for (int mt = 0; mt < 2; mt++)
                #pragma unroll
                for (int nt = 0; nt < 4; nt++) {
                    mma_bf16(tA[mt][nt], ah[mt], xbh[kt][nt]);
                    mma_bf16(tA[mt][nt], ah[mt], xbl[kt][nt]);
                    mma_bf16(tA[mt][nt], al[mt], xbh[kt][nt]);
                }
        }

        // --- fold gate weight, convert T c-frags -> stage-B a-frags ---
        unsigned th[2][2][4], tl[2][2][4];
        #pragma unroll
        for (int mt = 0; mt < 2; mt++)
            #pragma unroll
            for (int ktB = 0; ktB < 2; ktB++) {
                float c00 = w * tA[mt][2 * ktB][0],     c01 = w * tA[mt][2 * ktB][1];
                float c02 = w * tA[mt][2 * ktB][2],     c03 = w * tA[mt][2 * ktB][3];
                float c10 = w * tA[mt][2 * ktB + 1][0], c11 = w * tA[mt][2 * ktB + 1][1];
                float c12 = w * tA[mt][2 * ktB + 1][2], c13 = w * tA[mt][2 * ktB + 1][3];
                split_pair(c00, c01, th[mt][ktB][0], tl[mt][ktB][0]);   // row g,   k 2t..
                split_pair(c02, c03, th[mt][ktB][1], tl[mt][ktB][1]);   // row g+8, k 2t..
                split_pair(c10, c11, th[mt][ktB][2], tl[mt][ktB][2]);   // row g,   k 2t+8..
                split_pair(c12, c13, th[mt][ktB][3], tl[mt][ktB][3]);   // row g+8, k 2t+8..
            }

        // --- stage B: Y += T @ B^T, B row-major [p][j] is exactly mma's col B ---
        #pragma unroll
        for (int kt = 0; kt < 2; kt++)
            #pragma unroll
            for (int nt = 0; nt < 4; nt++) {
                const float* bp = Be + (size_t)e * 1024 + (nt * 8 + g) * 32 + kt * 16;
                float2 q0 = *(const float2*)(bp + 2 * t);
                float2 q1 = *(const float2*)(bp + 2 * t + 8);
                unsigned bh[2], bl[2];
                split_pair(q0.x, q0.y, bh[0], bl[0]);
                split_pair(q1.x, q1.y, bh[1], bl[1]);
                #pragma unroll
                for (int mt = 0; mt < 2; mt++) {
                    mma_bf16(Y[mt][nt], th[mt][kt], bh);
                    mma_bf16(Y[mt][nt], th[mt][kt], bl);
                    mma_bf16(Y[mt][nt], tl[mt][kt], bh);
                }
            }
    }

    // ---- epilogue: stage Y c-frags through smem, coalesced write ----
    __syncwarp();                 // X reads fully done before overwrite
    #pragma unroll
    for (int mt = 0; mt < 2; mt++)
        #pragma unroll
        for (int nt = 0; nt < 4; nt++) {
            int o0 = mt * 16 + g, p0 = nt * 8 + 2 * t;
            *(float2*)&xs[o0 * YSTRIDE + p0]       = make_float2(Y[mt][nt][0], Y[mt][nt][1]);
            *(float2*)&xs[(o0 + 8) * YSTRIDE + p0] = make_float2(Y[mt][nt][2], Y[mt][nt][3]);
        }
    __syncwarp();
    const float sc = *scale;
    float* og = out + (size_t)n * 1024;
    #pragma unroll
    for (int i = 0; i < 32; i++) {
        int q = i * 32 + lane;
        og[q] = xs[i * YSTRIDE + lane] * sc + bias[q];
    }
}

// ================================ launch ===================================
extern "C" void kernel_launch(void* const* d_in, const int* in_sizes, int n_in,
                              void* d_out, int out_size) {
    const float* x  = (const float*)d_in[0];
    const float* rw = (const float*)d_in[1];
    const float* Ae = (const float*)d_in[2];
    const float* Be = (const float*)d_in[3];
    const float* sc = (const float*)d_in[4];
    const float* bi = (const float*)d_in[5];
    float* out = (float*)d_out;

    const int M = in_sizes[0] / ROUTER_K;   // 16384
    const int E = in_sizes[1] / ROUTER_K;   // 256

    dim3 g1(M / R_BM, E / R_BN);
    router_mma_kernel<<<g1, 256>>>(x, rw, M, E);

    expert_fused_kernel<<<(M + TPB_TOK - 1) / TPB_TOK, 128>>>(
        x, rw, Ae, Be, sc, bi, out, M, E);
}

// round 5
// speedup vs baseline: 2.0713x; 1.6110x over previous
#include <cuda_runtime.h>
#include <cuda_bf16.h>
#include <math.h>

// ---------------------------------------------------------------------------
// KroneckerMoE v5:
//   K0: preconvert X,W fp32 -> bf16 (once)
//   K1: router logits via bf16 mma.sync m16n8k16 (bf16 operands from gmem)
//   K2: fused: approx top-4 -> exact fp32 re-rank (COALESCED) -> softmax ->
//       expert bilinear on tensor cores via bf16 3-term split
// ---------------------------------------------------------------------------

#define ROUTER_K   1024
#define MAX_TOKENS 16384
#define MAX_E      256

__device__ float    g_logits[(size_t)MAX_TOKENS * MAX_E];
__device__ unsigned g_xb[(size_t)MAX_TOKENS * (ROUTER_K / 2)];   // bf16x2
__device__ unsigned g_wb[(size_t)MAX_E * (ROUTER_K / 2)];        // bf16x2

// ======================= helpers =========================
__device__ __forceinline__ void mma_bf16(float d[4], const unsigned a[4], const unsigned b[2]) {
    asm volatile(
        "mma.sync.aligned.m16n8k16.row.col.f32.bf16.bf16.f32 "
        "{%0,%1,%2,%3}, {%4,%5,%6,%7}, {%8,%9}, {%0,%1,%2,%3};\n"
        : "+f"(d[0]), "+f"(d[1]), "+f"(d[2]), "+f"(d[3])
        : "r"(a[0]), "r"(a[1]), "r"(a[2]), "r"(a[3]), "r"(b[0]), "r"(b[1]));
}
__device__ __forceinline__ unsigned cvt2_bf16(float hi, float lo) {
    unsigned d;
    asm("cvt.rn.bf16x2.f32 %0, %1, %2;" : "=r"(d) : "f"(hi), "f"(lo));
    return d;
}
__device__ __forceinline__ float bf16lo_f(unsigned u) { return __uint_as_float(u << 16); }
__device__ __forceinline__ float bf16hi_f(unsigned u) { return __uint_as_float(u & 0xffff0000u); }
__device__ __forceinline__ void split_pair(float e0, float e1, unsigned& h, unsigned& l) {
    h = cvt2_bf16(e1, e0);
    float r0 = e0 - bf16lo_f(h);
    float r1 = e1 - bf16hi_f(h);
    l = cvt2_bf16(r1, r0);
}
__device__ __forceinline__ bool pair_better(float v, int i, float w, int j) {
    return (v > w) || (v == w && i < j);
}

// ======================= Kernel 0: fp32 -> bf16 preconvert ================
__global__ __launch_bounds__(256)
void convert_kernel(const float* __restrict__ X, const float* __restrict__ W,
                    int nx4, int nw4) {
    int i = blockIdx.x * blockDim.x + threadIdx.x;
    if (i < nx4) {
        float4 v = ((const float4*)X)[i];
        uint2 u = make_uint2(cvt2_bf16(v.y, v.x), cvt2_bf16(v.w, v.z));
        *(uint2*)&g_xb[2 * (size_t)i] = u;
    } else if (i < nx4 + nw4) {
        int j = i - nx4;
        float4 v = ((const float4*)W)[j];
        uint2 u = make_uint2(cvt2_bf16(v.y, v.x), cvt2_bf16(v.w, v.z));
        *(uint2*)&g_wb[2 * (size_t)j] = u;
    }
}

// ======================= Kernel 1: bf16 mma router ========================
#define R_BM 128
#define R_BN 64
#define R_BK 32
#define XPAD 20   // uint32 words per smem row (16 data + 4 pad)

__global__ __launch_bounds__(256)
void router_mma_kernel(int M, int E) {
    __shared__ unsigned Xs[R_BM][XPAD];
    __shared__ unsigned Ws[R_BN][XPAD];
    const int bm   = blockIdx.x * R_BM;
    const int bn   = blockIdx.y * R_BN;
    const int tid  = threadIdx.x;
    const int wid  = tid >> 5;
    const int lane = tid & 31;
    const int wm   = wid & 3;
    const int wn   = wid >> 2;
    const int g    = lane >> 2;
    const int t    = lane & 3;

    float d[2][4][4];
    #pragma unroll
    for (int mt = 0; mt < 2; mt++)
        #pragma unroll
        for (int nt = 0; nt < 4; nt++)
            #pragma unroll
            for (int r = 0; r < 4; r++) d[mt][nt][r] = 0.f;

    const uint4* xb4 = (const uint4*)g_xb;   // 128 uint4 per row
    const uint4* wb4 = (const uint4*)g_wb;

    for (int k0 = 0; k0 < ROUTER_K; k0 += R_BK) {
        // X tile 128 rows x 32 bf16 = 512 uint4 -> 2 per thread
        #pragma unroll
        for (int l = 0; l < 2; l++) {
            int id = tid + l * 256;
            int r  = id >> 2;
            int q  = id & 3;
            uint4 v = xb4[(size_t)(bm + r) * 128 + (k0 >> 3) + q];
            *(uint4*)&Xs[r][q * 4] = v;
        }
        // W tile 64 rows x 32 bf16 = 256 uint4 -> 1 per thread
        {
            int r = tid >> 2;
            int q = tid & 3;
            uint4 v = wb4[(size_t)(bn + r) * 128 + (k0 >> 3) + q];
            *(uint4*)&Ws[r][q * 4] = v;
        }
        __syncthreads();
        #pragma unroll
        for (int ks = 0; ks < 2; ks++) {
            const int kw = ks * 8 + t;
            unsigned a[2][4];
            #pragma unroll
            for (int mt = 0; mt < 2; mt++) {
                const int rb = wm * 32 + mt * 16;
                a[mt][0] = Xs[rb + g    ][kw];
                a[mt][1] = Xs[rb + g + 8][kw];
                a[mt][2] = Xs[rb + g    ][kw + 4];
                a[mt][3] = Xs[rb + g + 8][kw + 4];
            }
            unsigned b[4][2];
            #pragma unroll
            for (int nt = 0; nt < 4; nt++) {
                const int cb = wn * 32 + nt * 8;
                b[nt][0] = Ws[cb + g][kw];
                b[nt][1] = Ws[cb + g][kw + 4];
            }
            #pragma unroll
            for (int mt = 0; mt < 2; mt++)
                #pragma unroll
                for (int nt = 0; nt < 4; nt++)
                    mma_bf16(d[mt][nt], a[mt], b[nt]);
        }
        __syncthreads();
    }
    #pragma unroll
    for (int mt = 0; mt < 2; mt++) {
        #pragma unroll
        for (int nt = 0; nt < 4; nt++) {
            const int row = bm + wm * 32 + mt * 16 + g;
            const int col = bn + wn * 32 + nt * 8 + 2 * t;
            *(float2*)(g_logits + (size_t)row * E + col)       = make_float2(d[mt][nt][0], d[mt][nt][1]);
            *(float2*)(g_logits + (size_t)(row + 8) * E + col) = make_float2(d[mt][nt][2], d[mt][nt][3]);
        }
    }
}

// ============== Kernel 2: fused rerank + tensor-core expert ================
#define TPB_TOK 4
#define NCAND   4
#define XSTRIDE 36
#define YSTRIDE 34

__global__ __launch_bounds__(128)
void expert_fused_kernel(const float* __restrict__ x,
                         const float* __restrict__ RW,
                         const float* __restrict__ Ae,
                         const float* __restrict__ Be,
                         const float* __restrict__ scale,
                         const float* __restrict__ bias,
                         float* __restrict__ out, int M, int E) {
    __shared__ float XsAll[TPB_TOK][32 * XSTRIDE];
    const int wid  = threadIdx.x >> 5;
    const int lane = threadIdx.x & 31;
    const int n    = blockIdx.x * TPB_TOK + wid;
    if (n >= M) return;
    float* xs = XsAll[wid];
    const int g = lane >> 2;
    const int t = lane & 3;

    // ---- start logits loads early ----
    const int NJ = E >> 5;
    float lv[8];
    const float* lrow = g_logits + (size_t)n * E;
    #pragma unroll
    for (int j = 0; j < 8; j++) lv[j] = (j < NJ) ? lrow[lane + 32 * j] : -3.4e38f;

    // ---- load x row: smem tile + COALESCED reg chunks for rerank ----
    // xr4[q] holds x[(q*32+lane)*4 .. +3]  (consecutive lanes -> consecutive 16B)
    float4 xr4[8];
    {
        const float4* xg = (const float4*)(x + (size_t)n * 1024);
        #pragma unroll
        for (int i = 0; i < 8; i++) {
            int idx = i * 32 + lane;
            int r   = idx >> 3;
            int q   = idx & 7;
            float4 v = xg[idx];
            *(float4*)&xs[r * XSTRIDE + q * 4] = v;
        }
        #pragma unroll
        for (int q = 0; q < 8; q++) xr4[q] = xg[q * 32 + lane];   // L1-hot
    }
    __syncwarp();

    // ---- approx top-NCAND from bf16 logits ----
    int cand[NCAND];
    #pragma unroll
    for (int it = 0; it < NCAND; it++) {
        float bv = -3.4e38f; int be = 0x7fffffff;
        #pragma unroll
        for (int j = 0; j < 8; j++) {
            int e = lane + 32 * j;
            if (j < NJ && pair_better(lv[j], e, bv, be)) { bv = lv[j]; be = e; }
        }
        #pragma unroll
        for (int off = 16; off > 0; off >>= 1) {
            float ov = __shfl_xor_sync(0xffffffffu, bv, off);
            int   oe = __shfl_xor_sync(0xffffffffu, be, off);
            if (pair_better(ov, oe, bv, be)) { bv = ov; be = oe; }
        }
        cand[it] = be;
        if ((be & 31) == lane) lv[be >> 5] = -3.4e38f;
    }

    // ---- exact fp32 dots for candidates (coalesced) ----
    float s[NCAND];
    #pragma unroll
    for (int c = 0; c < NCAND; c++) {
        const float4* wr = (const float4*)(RW + (size_t)cand[c] * 1024);
        float acc = 0.f;
        #pragma unroll
        for (int q = 0; q < 8; q++) {
            float4 wv = wr[q * 32 + lane];
            acc += xr4[q].x * wv.x + xr4[q].y * wv.y + xr4[q].z * wv.z + xr4[q].w * wv.w;
        }
        s[c] = acc;
    }
    #pragma unroll
    for (int off = 16; off > 0; off >>= 1) {
        #pragma unroll
        for (int c = 0; c < NCAND; c++) s[c] += __shfl_xor_sync(0xffffffffu, s[c], off);
    }

    // ---- exact top-2 + softmax ----
    float v0 = s[0]; int c0 = 0;
    #pragma unroll
    for (int c = 1; c < NCAND; c++)
        if (pair_better(s[c], cand[c], v0, cand[c0])) { v0 = s[c]; c0 = c; }
    float v1 = -3.4e38f; int c1 = -1;
    #pragma unroll
    for (int c = 0; c < NCAND; c++)
        if (c != c0 && (c1 < 0 || pair_better(s[c], cand[c], v1, cand[c1]))) { v1 = s[c]; c1 = c; }
    const int e0 = cand[c0], e1 = cand[c1];
    const float tt = expf(v1 - v0);
    const float w0 = 1.f / (1.f + tt);
    const float w1 = tt * w0;

    // ---- build X b-fragments (bf16 hi/lo) once per token ----
    unsigned xbh[2][4][2], xbl[2][4][2];
    #pragma unroll
    for (int kt = 0; kt < 2; kt++)
        #pragma unroll
        for (int nt = 0; nt < 4; nt++)
            #pragma unroll
            for (int part = 0; part < 2; part++) {
                int krow = kt * 16 + 2 * t + 8 * part;
                float e0f = xs[krow * XSTRIDE + nt * 8 + g];
                float e1f = xs[(krow + 1) * XSTRIDE + nt * 8 + g];
                split_pair(e0f, e1f, xbh[kt][nt][part], xbl[kt][nt][part]);
            }

    // ---- per-expert: T = A@X, Y += w * T@B^T ----
    float Y[2][4][4];
    #pragma unroll
    for (int mt = 0; mt < 2; mt++)
        #pragma unroll
        for (int nt = 0; nt < 4; nt++)
            #pragma unroll
            for (int r = 0; r < 4; r++) Y[mt][nt][r] = 0.f;

    #pragma unroll
    for (int kk = 0; kk < 2; kk++) {
        const int   e = kk ? e1 : e0;
        const float w = kk ? w1 : w0;

        float tA[2][4][4];
        #pragma unroll
        for (int mt = 0; mt < 2; mt++)
            #pragma unroll
            for (int nt = 0; nt < 4; nt++)
                #pragma unroll
                for (int r = 0; r < 4; r++) tA[mt][nt][r] = 0.f;

        #pragma unroll
        for (int kt = 0; kt < 2; kt++) {
            unsigned ah[2][4], al[2][4];
            #pragma unroll
            for (int mt = 0; mt < 2; mt++) {
                const float* ap = Ae + (size_t)e * 1024 + (mt * 16 + g) * 32 + kt * 16;
                float2 p0 = *(const float2*)(ap + 2 * t);
                float2 p1 = *(const float2*)(ap + 2 * t + 8);
                float2 p2 = *(const float2*)(ap + 8 * 32 + 2 * t);
                float2 p3 = *(const float2*)(ap + 8 * 32 + 2 * t + 8);
                split_pair(p0.x, p0.y, ah[mt][0], al[mt][0]);
                split_pair(p2.x, p2.y, ah[mt][1], al[mt][1]);
                split_pair(p1.x, p1.y, ah[mt][2], al[mt][2]);
                split_pair(p3.x, p3.y, ah[mt][3], al[mt][3]);
            }
            #pragma unroll
            for (int mt = 0; mt < 2; mt++)
                #pragma unroll
                for (int nt = 0; nt < 4; nt++) {
                    mma_bf16(tA[mt][nt], ah[mt], xbh[kt][nt]);
                    mma_bf16(tA[mt][nt], ah[mt], xbl[kt][nt]);
                    mma_bf16(tA[mt][nt], al[mt], xbh[kt][nt]);
                }
        }

        unsigned th[2][2][4], tl[2][2][4];
        #pragma unroll
        for (int mt = 0; mt < 2; mt++)
            #pragma unroll
            for (int ktB = 0; ktB < 2; ktB++) {
                float c00 = w * tA[mt][2 * ktB][0],     c01 = w * tA[mt][2 * ktB][1];
                float c02 = w * tA[mt][2 * ktB][2],     c03 = w * tA[mt][2 * ktB][3];
                float c10 = w * tA[mt][2 * ktB + 1][0], c11 = w * tA[mt][2 * ktB + 1][1];
                float c12 = w * tA[mt][2 * ktB + 1][2], c13 = w * tA[mt][2 * ktB + 1][3];
                split_pair(c00, c01, th[mt][ktB][0], tl[mt][ktB][0]);
                split_pair(c02, c03, th[mt][ktB][1], tl[mt][ktB][1]);
                split_pair(c10, c11, th[mt][ktB][2], tl[mt][ktB][2]);
                split_pair(c12, c13, th[mt][ktB][3], tl[mt][ktB][3]);
            }

        #pragma unroll
        for (int kt = 0; kt < 2; kt++)
            #pragma unroll
            for (int nt = 0; nt < 4; nt++) {
                const float* bp = Be + (size_t)e * 1024 + (nt * 8 + g) * 32 + kt * 16;
                float2 q0 = *(const float2*)(bp + 2 * t);
                float2 q1 = *(const float2*)(bp + 2 * t + 8);
                unsigned bh[2], bl[2];
                split_pair(q0.x, q0.y, bh[0], bl[0]);
                split_pair(q1.x, q1.y, bh[1], bl[1]);
                #pragma unroll
                for (int mt = 0; mt < 2; mt++) {
                    mma_bf16(Y[mt][nt], th[mt][kt], bh);
                    mma_bf16(Y[mt][nt], th[mt][kt], bl);
                    mma_bf16(Y[mt][nt], tl[mt][kt], bh);
                }
            }
    }

    // ---- epilogue ----
    __syncwarp();
    #pragma unroll
    for (int mt = 0; mt < 2; mt++)
        #pragma unroll
        for (int nt = 0; nt < 4; nt++) {
            int o0 = mt * 16 + g, p0 = nt * 8 + 2 * t;
            *(float2*)&xs[o0 * YSTRIDE + p0]       = make_float2(Y[mt][nt][0], Y[mt][nt][1]);
            *(float2*)&xs[(o0 + 8) * YSTRIDE + p0] = make_float2(Y[mt][nt][2], Y[mt][nt][3]);
        }
    __syncwarp();
    const float sc = *scale;
    float* og = out + (size_t)n * 1024;
    #pragma unroll
    for (int i = 0; i < 32; i++) {
        int q = i * 32 + lane;
        og[q] = xs[i * YSTRIDE + lane] * sc + bias[q];
    }
}

// ================================ launch ===================================
extern "C" void kernel_launch(void* const* d_in, const int* in_sizes, int n_in,
                              void* d_out, int out_size) {
    const float* x  = (const float*)d_in[0];
    const float* rw = (const float*)d_in[1];
    const float* Ae = (const float*)d_in[2];
    const float* Be = (const float*)d_in[3];
    const float* sc = (const float*)d_in[4];
    const float* bi = (const float*)d_in[5];
    float* out = (float*)d_out;

    const int M = in_sizes[0] / ROUTER_K;   // 16384
    const int E = in_sizes[1] / ROUTER_K;   // 256

    const int nx4 = (M * ROUTER_K) / 4;
    const int nw4 = (E * ROUTER_K) / 4;
    convert_kernel<<<(nx4 + nw4 + 255) / 256, 256>>>(x, rw, nx4, nw4);

    dim3 g1(M / R_BM, E / R_BN);
    router_mma_kernel<<<g1, 256>>>(M, E);

    expert_fused_kernel<<<(M + TPB_TOK - 1) / TPB_TOK, 128>>>(
        x, rw, Ae, Be, sc, bi, out, M, E);
}

// round 6
// speedup vs baseline: 2.1493x; 1.0377x over previous
#include <cuda_runtime.h>
#include <cuda_bf16.h>
#include <math.h>

// ---------------------------------------------------------------------------
// KroneckerMoE v6:
//   K0: preconvert X,W fp32->bf16 AND pre-split A,B into mma-fragment
//       hi/lo bf16 arrays (grid tail of the same kernel)
//   K1: router logits via bf16 mma.sync m16n8k16
//   K2: fused: approx top-4 -> exact fp32 re-rank -> softmax ->
//       tensor-core expert bilinear (3-term bf16 split), A/B frags preloaded
// ---------------------------------------------------------------------------

#define ROUTER_K   1024
#define MAX_TOKENS 16384
#define MAX_E      256

__device__ float    g_logits[(size_t)MAX_TOKENS * MAX_E];
__device__ unsigned g_xb[(size_t)MAX_TOKENS * (ROUTER_K / 2)];   // bf16x2
__device__ unsigned g_wb[(size_t)MAX_E * (ROUTER_K / 2)];        // bf16x2
// A fragments: [e][kt][mt][lane] -> uint4 (a0..a3), hi and lo
__device__ uint4 g_Ah[MAX_E * 2 * 2 * 32];
__device__ uint4 g_Al[MAX_E * 2 * 2 * 32];
// B fragments: [e][kt][nt][lane] -> uint2 (b0..b1), hi and lo
__device__ uint2 g_Bh[MAX_E * 2 * 4 * 32];
__device__ uint2 g_Bl[MAX_E * 2 * 4 * 32];

// ======================= helpers =========================
__device__ __forceinline__ void mma_bf16(float d[4], const unsigned a[4], const unsigned b[2]) {
    asm volatile(
        "mma.sync.aligned.m16n8k16.row.col.f32.bf16.bf16.f32 "
        "{%0,%1,%2,%3}, {%4,%5,%6,%7}, {%8,%9}, {%0,%1,%2,%3};\n"
        : "+f"(d[0]), "+f"(d[1]), "+f"(d[2]), "+f"(d[3])
        : "r"(a[0]), "r"(a[1]), "r"(a[2]), "r"(a[3]), "r"(b[0]), "r"(b[1]));
}
__device__ __forceinline__ unsigned cvt2_bf16(float hi, float lo) {
    unsigned d;
    asm("cvt.rn.bf16x2.f32 %0, %1, %2;" : "=r"(d) : "f"(hi), "f"(lo));
    return d;
}
__device__ __forceinline__ float bf16lo_f(unsigned u) { return __uint_as_float(u << 16); }
__device__ __forceinline__ float bf16hi_f(unsigned u) { return __uint_as_float(u & 0xffff0000u); }
__device__ __forceinline__ void split_pair(float e0, float e1, unsigned& h, unsigned& l) {
    h = cvt2_bf16(e1, e0);
    float r0 = e0 - bf16lo_f(h);
    float r1 = e1 - bf16hi_f(h);
    l = cvt2_bf16(r1, r0);
}
__device__ __forceinline__ bool pair_better(float v, int i, float w, int j) {
    return (v > w) || (v == w && i < j);
}

// ========= Kernel 0: X,W bf16 convert + A,B fragment pre-split =============
__global__ __launch_bounds__(256)
void convert_kernel(const float* __restrict__ X, const float* __restrict__ W,
                    const float* __restrict__ Ae, const float* __restrict__ Be,
                    int nx4, int nw4, int E) {
    int i = blockIdx.x * blockDim.x + threadIdx.x;
    if (i < nx4) {
        float4 v = ((const float4*)X)[i];
        uint2 u = make_uint2(cvt2_bf16(v.y, v.x), cvt2_bf16(v.w, v.z));
        *(uint2*)&g_xb[2 * (size_t)i] = u;
    } else if (i < nx4 + nw4) {
        int j = i - nx4;
        float4 v = ((const float4*)W)[j];
        uint2 u = make_uint2(cvt2_bf16(v.y, v.x), cvt2_bf16(v.w, v.z));
        *(uint2*)&g_wb[2 * (size_t)j] = u;
    } else {
        int j = i - nx4 - nw4;          // one thread per (expert, lane)
        int e    = j >> 5;
        if (e >= E) return;
        int lane = j & 31;
        int g = lane >> 2, t = lane & 3;
        // --- A fragments ---
        #pragma unroll
        for (int kt = 0; kt < 2; kt++)
            #pragma unroll
            for (int mt = 0; mt < 2; mt++) {
                const float* ap = Ae + (size_t)e * 1024 + (mt * 16 + g) * 32 + kt * 16;
                float2 p0 = *(const float2*)(ap + 2 * t);
                float2 p1 = *(const float2*)(ap + 2 * t + 8);
                float2 p2 = *(const float2*)(ap + 8 * 32 + 2 * t);
                float2 p3 = *(const float2*)(ap + 8 * 32 + 2 * t + 8);
                uint4 h, l;
                split_pair(p0.x, p0.y, h.x, l.x);
                split_pair(p2.x, p2.y, h.y, l.y);
                split_pair(p1.x, p1.y, h.z, l.z);
                split_pair(p3.x, p3.y, h.w, l.w);
                int off = (((e * 2 + kt) * 2) + mt) * 32 + lane;
                g_Ah[off] = h;
                g_Al[off] = l;
            }
        // --- B fragments ---
        #pragma unroll
        for (int kt = 0; kt < 2; kt++)
            #pragma unroll
            for (int nt = 0; nt < 4; nt++) {
                const float* bp = Be + (size_t)e * 1024 + (nt * 8 + g) * 32 + kt * 16;
                float2 q0 = *(const float2*)(bp + 2 * t);
                float2 q1 = *(const float2*)(bp + 2 * t + 8);
                uint2 h, l;
                split_pair(q0.x, q0.y, h.x, l.x);
                split_pair(q1.x, q1.y, h.y, l.y);
                int off = (((e * 2 + kt) * 4) + nt) * 32 + lane;
                g_Bh[off] = h;
                g_Bl[off] = l;
            }
    }
}

// ======================= Kernel 1: bf16 mma router ========================
#define R_BM 128
#define R_BN 64
#define R_BK 32
#define XPAD 20

__global__ __launch_bounds__(256)
void router_mma_kernel(int M, int E) {
    __shared__ unsigned Xs[R_BM][XPAD];
    __shared__ unsigned Ws[R_BN][XPAD];
    const int bm   = blockIdx.x * R_BM;
    const int bn   = blockIdx.y * R_BN;
    const int tid  = threadIdx.x;
    const int wid  = tid >> 5;
    const int lane = tid & 31;
    const int wm   = wid & 3;
    const int wn   = wid >> 2;
    const int g    = lane >> 2;
    const int t    = lane & 3;

    float d[2][4][4];
    #pragma unroll
    for (int mt = 0; mt < 2; mt++)
        #pragma unroll
        for (int nt = 0; nt < 4; nt++)
            #pragma unroll
            for (int r = 0; r < 4; r++) d[mt][nt][r] = 0.f;

    const uint4* xb4 = (const uint4*)g_xb;
    const uint4* wb4 = (const uint4*)g_wb;

    for (int k0 = 0; k0 < ROUTER_K; k0 += R_BK) {
        #pragma unroll
        for (int l = 0; l < 2; l++) {
            int id = tid + l * 256;
            int r  = id >> 2;
            int q  = id & 3;
            uint4 v = xb4[(size_t)(bm + r) * 128 + (k0 >> 3) + q];
            *(uint4*)&Xs[r][q * 4] = v;
        }
        {
            int r = tid >> 2;
            int q = tid & 3;
            uint4 v = wb4[(size_t)(bn + r) * 128 + (k0 >> 3) + q];
            *(uint4*)&Ws[r][q * 4] = v;
        }
        __syncthreads();
        #pragma unroll
        for (int ks = 0; ks < 2; ks++) {
            const int kw = ks * 8 + t;
            unsigned a[2][4];
            #pragma unroll
            for (int mt = 0; mt < 2; mt++) {
                const int rb = wm * 32 + mt * 16;
                a[mt][0] = Xs[rb + g    ][kw];
                a[mt][1] = Xs[rb + g + 8][kw];
                a[mt][2] = Xs[rb + g    ][kw + 4];
                a[mt][3] = Xs[rb + g + 8][kw + 4];
            }
            unsigned b[4][2];
            #pragma unroll
            for (int nt = 0; nt < 4; nt++) {
                const int cb = wn * 32 + nt * 8;
                b[nt][0] = Ws[cb + g][kw];
                b[nt][1] = Ws[cb + g][kw + 4];
            }
            #pragma unroll
            for (int mt = 0; mt < 2; mt++)
                #pragma unroll
                for (int nt = 0; nt < 4; nt++)
                    mma_bf16(d[mt][nt], a[mt], b[nt]);
        }
        __syncthreads();
    }
    #pragma unroll
    for (int mt = 0; mt < 2; mt++) {
        #pragma unroll
        for (int nt = 0; nt < 4; nt++) {
            const int row = bm + wm * 32 + mt * 16 + g;
            const int col = bn + wn * 32 + nt * 8 + 2 * t;
            *(float2*)(g_logits + (size_t)row * E + col)       = make_float2(d[mt][nt][0], d[mt][nt][1]);
            *(float2*)(g_logits + (size_t)(row + 8) * E + col) = make_float2(d[mt][nt][2], d[mt][nt][3]);
        }
    }
}

// ============== Kernel 2: fused rerank + tensor-core expert ================
#define TPB_TOK 4
#define NCAND   4
#define XSTRIDE 36
#define YSTRIDE 34

__global__ __launch_bounds__(128)
void expert_fused_kernel(const float* __restrict__ x,
                         const float* __restrict__ RW,
                         const float* __restrict__ scale,
                         const float* __restrict__ bias,
                         float* __restrict__ out, int M, int E) {
    __shared__ float XsAll[TPB_TOK][32 * XSTRIDE];
    const int wid  = threadIdx.x >> 5;
    const int lane = threadIdx.x & 31;
    const int n    = blockIdx.x * TPB_TOK + wid;
    if (n >= M) return;
    float* xs = XsAll[wid];
    const int g = lane >> 2;
    const int t = lane & 3;

    // ---- start logits loads early ----
    const int NJ = E >> 5;
    float lv[8];
    const float* lrow = g_logits + (size_t)n * E;
    #pragma unroll
    for (int j = 0; j < 8; j++) lv[j] = (j < NJ) ? lrow[lane + 32 * j] : -3.4e38f;

    // ---- load x row: smem tile + coalesced reg chunks for rerank ----
    float4 xr4[8];
    {
        const float4* xg = (const float4*)(x + (size_t)n * 1024);
        #pragma unroll
        for (int i = 0; i < 8; i++) {
            int idx = i * 32 + lane;
            int r   = idx >> 3;
            int q   = idx & 7;
            float4 v = xg[idx];
            *(float4*)&xs[r * XSTRIDE + q * 4] = v;
        }
        #pragma unroll
        for (int q = 0; q < 8; q++) xr4[q] = xg[q * 32 + lane];
    }
    __syncwarp();

    // ---- approx top-NCAND from bf16 logits ----
    int cand[NCAND];
    #pragma unroll
    for (int it = 0; it < NCAND; it++) {
        float bv = -3.4e38f; int be = 0x7fffffff;
        #pragma unroll
        for (int j = 0; j < 8; j++) {
            int e = lane + 32 * j;
            if (j < NJ && pair_better(lv[j], e, bv, be)) { bv = lv[j]; be = e; }
        }
        #pragma unroll
        for (int off = 16; off > 0; off >>= 1) {
            float ov = __shfl_xor_sync(0xffffffffu, bv, off);
            int   oe = __shfl_xor_sync(0xffffffffu, be, off);
            if (pair_better(ov, oe, bv, be)) { bv = ov; be = oe; }
        }
        cand[it] = be;
        if ((be & 31) == lane) lv[be >> 5] = -3.4e38f;
    }

    // ---- exact fp32 dots for candidates (coalesced) ----
    float s[NCAND];
    #pragma unroll
    for (int c = 0; c < NCAND; c++) {
        const float4* wr = (const float4*)(RW + (size_t)cand[c] * 1024);
        float acc = 0.f;
        #pragma unroll
        for (int q = 0; q < 8; q++) {
            float4 wv = wr[q * 32 + lane];
            acc += xr4[q].x * wv.x + xr4[q].y * wv.y + xr4[q].z * wv.z + xr4[q].w * wv.w;
        }
        s[c] = acc;
    }
    #pragma unroll
    for (int off = 16; off > 0; off >>= 1) {
        #pragma unroll
        for (int c = 0; c < NCAND; c++) s[c] += __shfl_xor_sync(0xffffffffu, s[c], off);
    }

    // ---- exact top-2 + softmax ----
    float v0 = s[0]; int c0 = 0;
    #pragma unroll
    for (int c = 1; c < NCAND; c++)
        if (pair_better(s[c], cand[c], v0, cand[c0])) { v0 = s[c]; c0 = c; }
    float v1 = -3.4e38f; int c1 = -1;
    #pragma unroll
    for (int c = 0; c < NCAND; c++)
        if (c != c0 && (c1 < 0 || pair_better(s[c], cand[c], v1, cand[c1]))) { v1 = s[c]; c1 = c; }
    const int e0 = cand[c0], e1 = cand[c1];
    const float tt = expf(v1 - v0);
    const float w0 = 1.f / (1.f + tt);
    const float w1 = tt * w0;

    // ---- build X b-fragments (bf16 hi/lo) once per token ----
    unsigned xbh[2][4][2], xbl[2][4][2];
    #pragma unroll
    for (int kt = 0; kt < 2; kt++)
        #pragma unroll
        for (int nt = 0; nt < 4; nt++)
            #pragma unroll
            for (int part = 0; part < 2; part++) {
                int krow = kt * 16 + 2 * t + 8 * part;
                float e0f = xs[krow * XSTRIDE + nt * 8 + g];
                float e1f = xs[(krow + 1) * XSTRIDE + nt * 8 + g];
                split_pair(e0f, e1f, xbh[kt][nt][part], xbl[kt][nt][part]);
            }

    // ---- per-expert: T = A@X, Y += w * T@B^T ----
    float Y[2][4][4];
    #pragma unroll
    for (int mt = 0; mt < 2; mt++)
        #pragma unroll
        for (int nt = 0; nt < 4; nt++)
            #pragma unroll
            for (int r = 0; r < 4; r++) Y[mt][nt][r] = 0.f;

    #pragma unroll
    for (int kk = 0; kk < 2; kk++) {
        const int   e = kk ? e1 : e0;
        const float w = kk ? w1 : w0;

        float tA[2][4][4];
        #pragma unroll
        for (int mt = 0; mt < 2; mt++)
            #pragma unroll
            for (int nt = 0; nt < 4; nt++)
                #pragma unroll
                for (int r = 0; r < 4; r++) tA[mt][nt][r] = 0.f;

        // --- stage A: preloaded fragments, zero split arithmetic ---
        #pragma unroll
        for (int kt = 0; kt < 2; kt++) {
            #pragma unroll
            for (int mt = 0; mt < 2; mt++) {
                int off = (((e * 2 + kt) * 2) + mt) * 32 + lane;
                uint4 ah4 = g_Ah[off];
                uint4 al4 = g_Al[off];
                unsigned ah[4] = {ah4.x, ah4.y, ah4.z, ah4.w};
                unsigned al[4] = {al4.x, al4.y, al4.z, al4.w};
                #pragma unroll
                for (int nt = 0; nt < 4; nt++) {
                    mma_bf16(tA[mt][nt], ah, xbh[kt][nt]);
                    mma_bf16(tA[mt][nt], ah, xbl[kt][nt]);
                    mma_bf16(tA[mt][nt], al, xbh[kt][nt]);
                }
            }
        }

        // --- fold gate weight, convert T c-frags -> stage-B a-frags ---
        unsigned th[2][2][4], tl[2][2][4];
        #pragma unroll
        for (int mt = 0; mt < 2; mt++)
            #pragma unroll
            for (int ktB = 0; ktB < 2; ktB++) {
                float c00 = w * tA[mt][2 * ktB][0],     c01 = w * tA[mt][2 * ktB][1];
                float c02 = w * tA[mt][2 * ktB][2],     c03 = w * tA[mt][2 * ktB][3];
                float c10 = w * tA[mt][2 * ktB + 1][0], c11 = w * tA[mt][2 * ktB + 1][1];
                float c12 = w * tA[mt][2 * ktB + 1][2], c13 = w * tA[mt][2 * ktB + 1][3];
                split_pair(c00, c01, th[mt][ktB][0], tl[mt][ktB][0]);
                split_pair(c02, c03, th[mt][ktB][1], tl[mt][ktB][1]);
                split_pair(c10, c11, th[mt][ktB][2], tl[mt][ktB][2]);
                split_pair(c12, c13, th[mt][ktB][3], tl[mt][ktB][3]);
            }

        // --- stage B: preloaded B fragments ---
        #pragma unroll
        for (int kt = 0; kt < 2; kt++)
            #pragma unroll
            for (int nt = 0; nt < 4; nt++) {
                int off = (((e * 2 + kt) * 4) + nt) * 32 + lane;
                uint2 bh2 = g_Bh[off];
                uint2 bl2 = g_Bl[off];
                unsigned bh[2] = {bh2.x, bh2.y};
                unsigned bl[2] = {bl2.x, bl2.y};
                #pragma unroll
                for (int mt = 0; mt < 2; mt++) {
                    mma_bf16(Y[mt][nt], th[mt][kt], bh);
                    mma_bf16(Y[mt][nt], th[mt][kt], bl);
                    mma_bf16(Y[mt][nt], tl[mt][kt], bh);
                }
            }
    }

    // ---- epilogue ----
    __syncwarp();
    #pragma unroll
    for (int mt = 0; mt < 2; mt++)
        #pragma unroll
        for (int nt = 0; nt < 4; nt++) {
            int o0 = mt * 16 + g, p0 = nt * 8 + 2 * t;
            *(float2*)&xs[o0 * YSTRIDE + p0]       = make_float2(Y[mt][nt][0], Y[mt][nt][1]);
            *(float2*)&xs[(o0 + 8) * YSTRIDE + p0] = make_float2(Y[mt][nt][2], Y[mt][nt][3]);
        }
    __syncwarp();
    const float sc = *scale;
    float* og = out + (size_t)n * 1024;
    #pragma unroll
    for (int i = 0; i < 32; i++) {
        int q = i * 32 + lane;
        og[q] = xs[i * YSTRIDE + lane] * sc + bias[q];
    }
}

// ================================ launch ===================================
extern "C" void kernel_launch(void* const* d_in, const int* in_sizes, int n_in,
                              void* d_out, int out_size) {
    const float* x  = (const float*)d_in[0];
    const float* rw = (const float*)d_in[1];
    const float* Ae = (const float*)d_in[2];
    const float* Be = (const float*)d_in[3];
    const float* sc = (const float*)d_in[4];
    const float* bi = (const float*)d_in[5];
    float* out = (float*)d_out;

    const int M = in_sizes[0] / ROUTER_K;   // 16384
    const int E = in_sizes[1] / ROUTER_K;   // 256

    const int nx4 = (M * ROUTER_K) / 4;
    const int nw4 = (E * ROUTER_K) / 4;
    const int nfrag = E * 32;
    convert_kernel<<<(nx4 + nw4 + nfrag + 255) / 256, 256>>>(x, rw, Ae, Be, nx4, nw4, E);

    dim3 g1(M / R_BM, E / R_BN);
    router_mma_kernel<<<g1, 256>>>(M, E);

    expert_fused_kernel<<<(M + TPB_TOK - 1) / TPB_TOK, 128>>>(
        x, rw, sc, bi, out, M, E);
}

// round 7
// speedup vs baseline: 2.2953x; 1.0679x over previous
#include <cuda_runtime.h>
#include <cuda_bf16.h>
#include <math.h>

// ---------------------------------------------------------------------------
// KroneckerMoE v7:
//   K0: preconvert X,W fp32->bf16 (32B/thread) + pre-split A,B mma fragments
//   K1: router logits via bf16 mma.sync, 2-stage cp.async double buffer
//   K2: fused: approx top-4 -> exact fp32 re-rank -> softmax ->
//       tensor-core expert bilinear (3-term bf16 split), A/B frags preloaded
// ---------------------------------------------------------------------------

#define ROUTER_K   1024
#define MAX_TOKENS 16384
#define MAX_E      256

__device__ float    g_logits[(size_t)MAX_TOKENS * MAX_E];
__device__ unsigned g_xb[(size_t)MAX_TOKENS * (ROUTER_K / 2)];   // bf16x2
__device__ unsigned g_wb[(size_t)MAX_E * (ROUTER_K / 2)];        // bf16x2
__device__ uint4 g_Ah[MAX_E * 2 * 2 * 32];
__device__ uint4 g_Al[MAX_E * 2 * 2 * 32];
__device__ uint2 g_Bh[MAX_E * 2 * 4 * 32];
__device__ uint2 g_Bl[MAX_E * 2 * 4 * 32];

// ======================= helpers =========================
__device__ __forceinline__ void mma_bf16(float d[4], const unsigned a[4], const unsigned b[2]) {
    asm volatile(
        "mma.sync.aligned.m16n8k16.row.col.f32.bf16.bf16.f32 "
        "{%0,%1,%2,%3}, {%4,%5,%6,%7}, {%8,%9}, {%0,%1,%2,%3};\n"
        : "+f"(d[0]), "+f"(d[1]), "+f"(d[2]), "+f"(d[3])
        : "r"(a[0]), "r"(a[1]), "r"(a[2]), "r"(a[3]), "r"(b[0]), "r"(b[1]));
}
__device__ __forceinline__ unsigned cvt2_bf16(float hi, float lo) {
    unsigned d;
    asm("cvt.rn.bf16x2.f32 %0, %1, %2;" : "=r"(d) : "f"(hi), "f"(lo));
    return d;
}
__device__ __forceinline__ float bf16lo_f(unsigned u) { return __uint_as_float(u << 16); }
__device__ __forceinline__ float bf16hi_f(unsigned u) { return __uint_as_float(u & 0xffff0000u); }
__device__ __forceinline__ void split_pair(float e0, float e1, unsigned& h, unsigned& l) {
    h = cvt2_bf16(e1, e0);
    float r0 = e0 - bf16lo_f(h);
    float r1 = e1 - bf16hi_f(h);
    l = cvt2_bf16(r1, r0);
}
__device__ __forceinline__ bool pair_better(float v, int i, float w, int j) {
    return (v > w) || (v == w && i < j);
}
__device__ __forceinline__ void cp_async16(void* smem, const void* gmem) {
    unsigned s = (unsigned)__cvta_generic_to_shared(smem);
    asm volatile("cp.async.cg.shared.global [%0], [%1], 16;" :: "r"(s), "l"(gmem));
}

// ========= Kernel 0: X,W bf16 convert (32B/thread) + A,B frag split ========
__global__ __launch_bounds__(256)
void convert_kernel(const float* __restrict__ X, const float* __restrict__ W,
                    const float* __restrict__ Ae, const float* __restrict__ Be,
                    int nx8, int nw8, int E) {
    int i = blockIdx.x * blockDim.x + threadIdx.x;
    if (i < nx8) {
        float4 v0 = ((const float4*)X)[2 * (size_t)i];
        float4 v1 = ((const float4*)X)[2 * (size_t)i + 1];
        uint4 u = make_uint4(cvt2_bf16(v0.y, v0.x), cvt2_bf16(v0.w, v0.z),
                             cvt2_bf16(v1.y, v1.x), cvt2_bf16(v1.w, v1.z));
        ((uint4*)g_xb)[i] = u;
    } else if (i < nx8 + nw8) {
        int j = i - nx8;
        float4 v0 = ((const float4*)W)[2 * (size_t)j];
        float4 v1 = ((const float4*)W)[2 * (size_t)j + 1];
        uint4 u = make_uint4(cvt2_bf16(v0.y, v0.x), cvt2_bf16(v0.w, v0.z),
                             cvt2_bf16(v1.y, v1.x), cvt2_bf16(v1.w, v1.z));
        ((uint4*)g_wb)[j] = u;
    } else {
        int j = i - nx8 - nw8;
        int e = j >> 5;
        if (e >= E) return;
        int lane = j & 31;
        int g = lane >> 2, t = lane & 3;
        #pragma unroll
        for (int kt = 0; kt < 2; kt++)
            #pragma unroll
            for (int mt = 0; mt < 2; mt++) {
                const float* ap = Ae + (size_t)e * 1024 + (mt * 16 + g) * 32 + kt * 16;
                float2 p0 = *(const float2*)(ap + 2 * t);
                float2 p1 = *(const float2*)(ap + 2 * t + 8);
                float2 p2 = *(const float2*)(ap + 8 * 32 + 2 * t);
                float2 p3 = *(const float2*)(ap + 8 * 32 + 2 * t + 8);
                uint4 h, l;
                split_pair(p0.x, p0.y, h.x, l.x);
                split_pair(p2.x, p2.y, h.y, l.y);
                split_pair(p1.x, p1.y, h.z, l.z);
                split_pair(p3.x, p3.y, h.w, l.w);
                int off = (((e * 2 + kt) * 2) + mt) * 32 + lane;
                g_Ah[off] = h;
                g_Al[off] = l;
            }
        #pragma unroll
        for (int kt = 0; kt < 2; kt++)
            #pragma unroll
            for (int nt = 0; nt < 4; nt++) {
                const float* bp = Be + (size_t)e * 1024 + (nt * 8 + g) * 32 + kt * 16;
                float2 q0 = *(const float2*)(bp + 2 * t);
                float2 q1 = *(const float2*)(bp + 2 * t + 8);
                uint2 h, l;
                split_pair(q0.x, q0.y, h.x, l.x);
                split_pair(q1.x, q1.y, h.y, l.y);
                int off = (((e * 2 + kt) * 4) + nt) * 32 + lane;
                g_Bh[off] = h;
                g_Bl[off] = l;
            }
    }
}

// ========== Kernel 1: bf16 mma router, cp.async double buffer ==============
#define R_BM 128
#define R_BN 64
#define R_BK 32
#define XPAD 20
#define R_NI (ROUTER_K / R_BK)   // 32

__global__ __launch_bounds__(256)
void router_mma_kernel(int M, int E) {
    __shared__ unsigned Xs[2][R_BM][XPAD];
    __shared__ unsigned Ws[2][R_BN][XPAD];
    const int bm   = blockIdx.x * R_BM;
    const int bn   = blockIdx.y * R_BN;
    const int tid  = threadIdx.x;
    const int wid  = tid >> 5;
    const int lane = tid & 31;
    const int wm   = wid & 3;
    const int wn   = wid >> 2;
    const int g    = lane >> 2;
    const int t    = lane & 3;

    float d[2][4][4];
    #pragma unroll
    for (int mt = 0; mt < 2; mt++)
        #pragma unroll
        for (int nt = 0; nt < 4; nt++)
            #pragma unroll
            for (int r = 0; r < 4; r++) d[mt][nt][r] = 0.f;

    const uint4* xb4 = (const uint4*)g_xb;   // 128 uint4 per row
    const uint4* wb4 = (const uint4*)g_wb;

    // indices for this thread's async copies
    const int xr0 = tid >> 2;            // 0..63   (X row for l=0)
    const int xr1 = (tid + 256) >> 2;    // 64..127 (X row for l=1)
    const int xq  = tid & 3;
    const int wr  = tid >> 2;
    const int wq  = tid & 3;

    // prologue: stage 0
    {
        cp_async16(&Xs[0][xr0][xq * 4], &xb4[(size_t)(bm + xr0) * 128 + xq]);
        cp_async16(&Xs[0][xr1][xq * 4], &xb4[(size_t)(bm + xr1) * 128 + xq]);
        cp_async16(&Ws[0][wr][wq * 4],  &wb4[(size_t)(bn + wr) * 128 + wq]);
        asm volatile("cp.async.commit_group;");
    }

    for (int it = 0; it < R_NI; it++) {
        const int s = it & 1;
        if (it + 1 < R_NI) {
            const int kq = (it + 1) * 4;
            const int s1 = s ^ 1;
            cp_async16(&Xs[s1][xr0][xq * 4], &xb4[(size_t)(bm + xr0) * 128 + kq + xq]);
            cp_async16(&Xs[s1][xr1][xq * 4], &xb4[(size_t)(bm + xr1) * 128 + kq + xq]);
            cp_async16(&Ws[s1][wr][wq * 4],  &wb4[(size_t)(bn + wr) * 128 + kq + wq]);
            asm volatile("cp.async.commit_group;");
            asm volatile("cp.async.wait_group 1;");
        } else {
            asm volatile("cp.async.wait_group 0;");
        }
        __syncthreads();

        #pragma unroll
        for (int ks = 0; ks < 2; ks++) {
            const int kw = ks * 8 + t;
            unsigned a[2][4];
            #pragma unroll
            for (int mt = 0; mt < 2; mt++) {
                const int rb = wm * 32 + mt * 16;
                a[mt][0] = Xs[s][rb + g    ][kw];
                a[mt][1] = Xs[s][rb + g + 8][kw];
                a[mt][2] = Xs[s][rb + g    ][kw + 4];
                a[mt][3] = Xs[s][rb + g + 8][kw + 4];
            }
            unsigned b[4][2];
            #pragma unroll
            for (int nt = 0; nt < 4; nt++) {
                const int cb = wn * 32 + nt * 8;
                b[nt][0] = Ws[s][cb + g][kw];
                b[nt][1] = Ws[s][cb + g][kw + 4];
            }
            #pragma unroll
            for (int mt = 0; mt < 2; mt++)
                #pragma unroll
                for (int nt = 0; nt < 4; nt++)
                    mma_bf16(d[mt][nt], a[mt], b[nt]);
        }
        __syncthreads();
    }

    #pragma unroll
    for (int mt = 0; mt < 2; mt++) {
        #pragma unroll
        for (int nt = 0; nt < 4; nt++) {
            const int row = bm + wm * 32 + mt * 16 + g;
            const int col = bn + wn * 32 + nt * 8 + 2 * t;
            *(float2*)(g_logits + (size_t)row * E + col)       = make_float2(d[mt][nt][0], d[mt][nt][1]);
            *(float2*)(g_logits + (size_t)(row + 8) * E + col) = make_float2(d[mt][nt][2], d[mt][nt][3]);
        }
    }
}

// ============== Kernel 2: fused rerank + tensor-core expert ================
#define TPB_TOK 4
#define NCAND   4
#define XSTRIDE 36
#define YSTRIDE 34

__global__ __launch_bounds__(128)
void expert_fused_kernel(const float* __restrict__ x,
                         const float* __restrict__ RW,
                         const float* __restrict__ scale,
                         const float* __restrict__ bias,
                         float* __restrict__ out, int M, int E) {
    __shared__ float XsAll[TPB_TOK][32 * XSTRIDE];
    const int wid  = threadIdx.x >> 5;
    const int lane = threadIdx.x & 31;
    const int n    = blockIdx.x * TPB_TOK + wid;
    if (n >= M) return;
    float* xs = XsAll[wid];
    const int g = lane >> 2;
    const int t = lane & 3;

    const int NJ = E >> 5;
    float lv[8];
    const float* lrow = g_logits + (size_t)n * E;
    #pragma unroll
    for (int j = 0; j < 8; j++) lv[j] = (j < NJ) ? lrow[lane + 32 * j] : -3.4e38f;

    float4 xr4[8];
    {
        const float4* xg = (const float4*)(x + (size_t)n * 1024);
        #pragma unroll
        for (int i = 0; i < 8; i++) {
            int idx = i * 32 + lane;
            int r   = idx >> 3;
            int q   = idx & 7;
            float4 v = xg[idx];
            *(float4*)&xs[r * XSTRIDE + q * 4] = v;
        }
        #pragma unroll
        for (int q = 0; q < 8; q++) xr4[q] = xg[q * 32 + lane];
    }
    __syncwarp();

    int cand[NCAND];
    #pragma unroll
    for (int it = 0; it < NCAND; it++) {
        float bv = -3.4e38f; int be = 0x7fffffff;
        #pragma unroll
        for (int j = 0; j < 8; j++) {
            int e = lane + 32 * j;
            if (j < NJ && pair_better(lv[j], e, bv, be)) { bv = lv[j]; be = e; }
        }
        #pragma unroll
        for (int off = 16; off > 0; off >>= 1) {
            float ov = __shfl_xor_sync(0xffffffffu, bv, off);
            int   oe = __shfl_xor_sync(0xffffffffu, be, off);
            if (pair_better(ov, oe, bv, be)) { bv = ov; be = oe; }
        }
        cand[it] = be;
        if ((be & 31) == lane) lv[be >> 5] = -3.4e38f;
    }

    float s[NCAND];
    #pragma unroll
    for (int c = 0; c < NCAND; c++) {
        const float4* wr = (const float4*)(RW + (size_t)cand[c] * 1024);
        float acc = 0.f;
        #pragma unroll
        for (int q = 0; q < 8; q++) {
            float4 wv = wr[q * 32 + lane];
            acc += xr4[q].x * wv.x + xr4[q].y * wv.y + xr4[q].z * wv.z + xr4[q].w * wv.w;
        }
        s[c] = acc;
    }
    #pragma unroll
    for (int off = 16; off > 0; off >>= 1) {
        #pragma unroll
        for (int c = 0; c < NCAND; c++) s[c] += __shfl_xor_sync(0xffffffffu, s[c], off);
    }

    float v0 = s[0]; int c0 = 0;
    #pragma unroll
    for (int c = 1; c < NCAND; c++)
        if (pair_better(s[c], cand[c], v0, cand[c0])) { v0 = s[c]; c0 = c; }
    float v1 = -3.4e38f; int c1 = -1;
    #pragma unroll
    for (int c = 0; c < NCAND; c++)
        if (c != c0 && (c1 < 0 || pair_better(s[c], cand[c], v1, cand[c1]))) { v1 = s[c]; c1 = c; }
    const int e0 = cand[c0], e1 = cand[c1];
    const float tt = expf(v1 - v0);
    const float w0 = 1.f / (1.f + tt);
    const float w1 = tt * w0;

    unsigned xbh[2][4][2], xbl[2][4][2];
    #pragma unroll
    for (int kt = 0; kt < 2; kt++)
        #pragma unroll
        for (int nt = 0; nt < 4; nt++)
            #pragma unroll
            for (int part = 0; part < 2; part++) {
                int krow = kt * 16 + 2 * t + 8 * part;
                float e0f = xs[krow * XSTRIDE + nt * 8 + g];
                float e1f = xs[(krow + 1) * XSTRIDE + nt * 8 + g];
                split_pair(e0f, e1f, xbh[kt][nt][part], xbl[kt][nt][part]);
            }

    float Y[2][4][4];
    #pragma unroll
    for (int mt = 0; mt < 2; mt++)
        #pragma unroll
        for (int nt = 0; nt < 4; nt++)
            #pragma unroll
            for (int r = 0; r < 4; r++) Y[mt][nt][r] = 0.f;

    #pragma unroll
    for (int kk = 0; kk < 2; kk++) {
        const int   e = kk ? e1 : e0;
        const float w = kk ? w1 : w0;

        float tA[2][4][4];
        #pragma unroll
        for (int mt = 0; mt < 2; mt++)
            #pragma unroll
            for (int nt = 0; nt < 4; nt++)
                #pragma unroll
                for (int r = 0; r < 4; r++) tA[mt][nt][r] = 0.f;

        #pragma unroll
        for (int kt = 0; kt < 2; kt++) {
            #pragma unroll
            for (int mt = 0; mt < 2; mt++) {
                int off = (((e * 2 + kt) * 2) + mt) * 32 + lane;
                uint4 ah4 = g_Ah[off];
                uint4 al4 = g_Al[off];
                unsigned ah[4] = {ah4.x, ah4.y, ah4.z, ah4.w};
                unsigned al[4] = {al4.x, al4.y, al4.z, al4.w};
                #pragma unroll
                for (int nt = 0; nt < 4; nt++) {
                    mma_bf16(tA[mt][nt], ah, xbh[kt][nt]);
                    mma_bf16(tA[mt][nt], ah, xbl[kt][nt]);
                    mma_bf16(tA[mt][nt], al, xbh[kt][nt]);
                }
            }
        }

        unsigned th[2][2][4], tl[2][2][4];
        #pragma unroll
        for (int mt = 0; mt < 2; mt++)
            #pragma unroll
            for (int ktB = 0; ktB < 2; ktB++) {
                float c00 = w * tA[mt][2 * ktB][0],     c01 = w * tA[mt][2 * ktB][1];
                float c02 = w * tA[mt][2 * ktB][2],     c03 = w * tA[mt][2 * ktB][3];
                float c10 = w * tA[mt][2 * ktB + 1][0], c11 = w * tA[mt][2 * ktB + 1][1];
                float c12 = w * tA[mt][2 * ktB + 1][2], c13 = w * tA[mt][2 * ktB + 1][3];
                split_pair(c00, c01, th[mt][ktB][0], tl[mt][ktB][0]);
                split_pair(c02, c03, th[mt][ktB][1], tl[mt][ktB][1]);
                split_pair(c10, c11, th[mt][ktB][2], tl[mt][ktB][2]);
                split_pair(c12, c13, th[mt][ktB][3], tl[mt][ktB][3]);
            }

        #pragma unroll
        for (int kt = 0; kt < 2; kt++)
            #pragma unroll
            for (int nt = 0; nt < 4; nt++) {
                int off = (((e * 2 + kt) * 4) + nt) * 32 + lane;
                uint2 bh2 = g_Bh[off];
                uint2 bl2 = g_Bl[off];
                unsigned bh[2] = {bh2.x, bh2.y};
                unsigned bl[2] = {bl2.x, bl2.y};
                #pragma unroll
                for (int mt = 0; mt < 2; mt++) {
                    mma_bf16(Y[mt][nt], th[mt][kt], bh);
                    mma_bf16(Y[mt][nt], th[mt][kt], bl);
                    mma_bf16(Y[mt][nt], tl[mt][kt], bh);
                }
            }
    }

    __syncwarp();
    #pragma unroll
    for (int mt = 0; mt < 2; mt++)
        #pragma unroll
        for (int nt = 0; nt < 4; nt++) {
            int o0 = mt * 16 + g, p0 = nt * 8 + 2 * t;
            *(float2*)&xs[o0 * YSTRIDE + p0]       = make_float2(Y[mt][nt][0], Y[mt][nt][1]);
            *(float2*)&xs[(o0 + 8) * YSTRIDE + p0] = make_float2(Y[mt][nt][2], Y[mt][nt][3]);
        }
    __syncwarp();
    const float sc = *scale;
    float* og = out + (size_t)n * 1024;
    #pragma unroll
    for (int i = 0; i < 32; i++) {
        int q = i * 32 + lane;
        og[q] = xs[i * YSTRIDE + lane] * sc + bias[q];
    }
}

// ================================ launch ===================================
extern "C" void kernel_launch(void* const* d_in, const int* in_sizes, int n_in,
                              void* d_out, int out_size) {
    const float* x  = (const float*)d_in[0];
    const float* rw = (const float*)d_in[1];
    const float* Ae = (const float*)d_in[2];
    const float* Be = (const float*)d_in[3];
    const float* sc = (const float*)d_in[4];
    const float* bi = (const float*)d_in[5];
    float* out = (float*)d_out;

    const int M = in_sizes[0] / ROUTER_K;   // 16384
    const int E = in_sizes[1] / ROUTER_K;   // 256

    const int nx8 = (M * ROUTER_K) / 8;
    const int nw8 = (E * ROUTER_K) / 8;
    const int nfrag = E * 32;
    convert_kernel<<<(nx8 + nw8 + nfrag + 255) / 256, 256>>>(x, rw, Ae, Be, nx8, nw8, E);

    dim3 g1(M / R_BM, E / R_BN);
    router_mma_kernel<<<g1, 256>>>(M, E);

    expert_fused_kernel<<<(M + TPB_TOK - 1) / TPB_TOK, 128>>>(
        x, rw, sc, bi, out, M, E);
}

// round 8
// speedup vs baseline: 2.4054x; 1.0480x over previous
#include <cuda_runtime.h>
#include <cuda_bf16.h>
#include <math.h>

// ---------------------------------------------------------------------------
// KroneckerMoE v8:
//   K0: preconvert X,W fp32->bf16 + pre-split A,B mma fragments
//   K1: router logits, bf16 mma.sync, 3-stage cp.async, 1 sync/iter
//   K2a: routing: approx top-4 -> exact fp32 rerank -> softmax -> route table
//   K2b: expert compute: tensor-core bilinear (3-term bf16 split), low-reg
// ---------------------------------------------------------------------------

#define ROUTER_K   1024
#define MAX_TOKENS 16384
#define MAX_E      256

__device__ float    g_logits[(size_t)MAX_TOKENS * MAX_E];
__device__ unsigned g_xb[(size_t)MAX_TOKENS * (ROUTER_K / 2)];   // bf16x2
__device__ unsigned g_wb[(size_t)MAX_E * (ROUTER_K / 2)];        // bf16x2
__device__ uint4 g_Ah[MAX_E * 2 * 2 * 32];
__device__ uint4 g_Al[MAX_E * 2 * 2 * 32];
__device__ uint2 g_Bh[MAX_E * 2 * 4 * 32];
__device__ uint2 g_Bl[MAX_E * 2 * 4 * 32];
__device__ int2   g_eidx[MAX_TOKENS];
__device__ float2 g_gate[MAX_TOKENS];

// ======================= helpers =========================
__device__ __forceinline__ void mma_bf16(float d[4], const unsigned a[4], const unsigned b[2]) {
    asm volatile(
        "mma.sync.aligned.m16n8k16.row.col.f32.bf16.bf16.f32 "
        "{%0,%1,%2,%3}, {%4,%5,%6,%7}, {%8,%9}, {%0,%1,%2,%3};\n"
        : "+f"(d[0]), "+f"(d[1]), "+f"(d[2]), "+f"(d[3])
        : "r"(a[0]), "r"(a[1]), "r"(a[2]), "r"(a[3]), "r"(b[0]), "r"(b[1]));
}
__device__ __forceinline__ unsigned cvt2_bf16(float hi, float lo) {
    unsigned d;
    asm("cvt.rn.bf16x2.f32 %0, %1, %2;" : "=r"(d) : "f"(hi), "f"(lo));
    return d;
}
__device__ __forceinline__ float bf16lo_f(unsigned u) { return __uint_as_float(u << 16); }
__device__ __forceinline__ float bf16hi_f(unsigned u) { return __uint_as_float(u & 0xffff0000u); }
__device__ __forceinline__ void split_pair(float e0, float e1, unsigned& h, unsigned& l) {
    h = cvt2_bf16(e1, e0);
    float r0 = e0 - bf16lo_f(h);
    float r1 = e1 - bf16hi_f(h);
    l = cvt2_bf16(r1, r0);
}
__device__ __forceinline__ bool pair_better(float v, int i, float w, int j) {
    return (v > w) || (v == w && i < j);
}
__device__ __forceinline__ void cp_async16(void* smem, const void* gmem) {
    unsigned s = (unsigned)__cvta_generic_to_shared(smem);
    asm volatile("cp.async.cg.shared.global [%0], [%1], 16;" :: "r"(s), "l"(gmem));
}

// ========= Kernel 0: X,W bf16 convert + A,B frag split ========
__global__ __launch_bounds__(256)
void convert_kernel(const float* __restrict__ X, const float* __restrict__ W,
                    const float* __restrict__ Ae, const float* __restrict__ Be,
                    int nx8, int nw8, int E) {
    int i = blockIdx.x * blockDim.x + threadIdx.x;
    if (i < nx8) {
        float4 v0 = ((const float4*)X)[2 * (size_t)i];
        float4 v1 = ((const float4*)X)[2 * (size_t)i + 1];
        uint4 u = make_uint4(cvt2_bf16(v0.y, v0.x), cvt2_bf16(v0.w, v0.z),
                             cvt2_bf16(v1.y, v1.x), cvt2_bf16(v1.w, v1.z));
        ((uint4*)g_xb)[i] = u;
    } else if (i < nx8 + nw8) {
        int j = i - nx8;
        float4 v0 = ((const float4*)W)[2 * (size_t)j];
        float4 v1 = ((const float4*)W)[2 * (size_t)j + 1];
        uint4 u = make_uint4(cvt2_bf16(v0.y, v0.x), cvt2_bf16(v0.w, v0.z),
                             cvt2_bf16(v1.y, v1.x), cvt2_bf16(v1.w, v1.z));
        ((uint4*)g_wb)[j] = u;
    } else {
        int j = i - nx8 - nw8;
        int e = j >> 5;
        if (e >= E) return;
        int lane = j & 31;
        int g = lane >> 2, t = lane & 3;
        #pragma unroll
        for (int kt = 0; kt < 2; kt++)
            #pragma unroll
            for (int mt = 0; mt < 2; mt++) {
                const float* ap = Ae + (size_t)e * 1024 + (mt * 16 + g) * 32 + kt * 16;
                float2 p0 = *(const float2*)(ap + 2 * t);
                float2 p1 = *(const float2*)(ap + 2 * t + 8);
                float2 p2 = *(const float2*)(ap + 8 * 32 + 2 * t);
                float2 p3 = *(const float2*)(ap + 8 * 32 + 2 * t + 8);
                uint4 h, l;
                split_pair(p0.x, p0.y, h.x, l.x);
                split_pair(p2.x, p2.y, h.y, l.y);
                split_pair(p1.x, p1.y, h.z, l.z);
                split_pair(p3.x, p3.y, h.w, l.w);
                int off = (((e * 2 + kt) * 2) + mt) * 32 + lane;
                g_Ah[off] = h;
                g_Al[off] = l;
            }
        #pragma unroll
        for (int kt = 0; kt < 2; kt++)
            #pragma unroll
            for (int nt = 0; nt < 4; nt++) {
                const float* bp = Be + (size_t)e * 1024 + (nt * 8 + g) * 32 + kt * 16;
                float2 q0 = *(const float2*)(bp + 2 * t);
                float2 q1 = *(const float2*)(bp + 2 * t + 8);
                uint2 h, l;
                split_pair(q0.x, q0.y, h.x, l.x);
                split_pair(q1.x, q1.y, h.y, l.y);
                int off = (((e * 2 + kt) * 4) + nt) * 32 + lane;
                g_Bh[off] = h;
                g_Bl[off] = l;
            }
    }
}

// ========== Kernel 1: bf16 mma router, 3-stage cp.async ==============
#define R_BM 128
#define R_BN 64
#define R_BK 32
#define XPAD 20
#define R_NI (ROUTER_K / R_BK)   // 32
#define NSTAGE 3

__global__ __launch_bounds__(256)
void router_mma_kernel(int M, int E) {
    __shared__ unsigned Xs[NSTAGE][R_BM][XPAD];
    __shared__ unsigned Ws[NSTAGE][R_BN][XPAD];
    const int bm   = blockIdx.x * R_BM;
    const int bn   = blockIdx.y * R_BN;
    const int tid  = threadIdx.x;
    const int wid  = tid >> 5;
    const int lane = tid & 31;
    const int wm   = wid & 3;
    const int wn   = wid >> 2;
    const int g    = lane >> 2;
    const int t    = lane & 3;

    float d[2][4][4];
    #pragma unroll
    for (int mt = 0; mt < 2; mt++)
        #pragma unroll
        for (int nt = 0; nt < 4; nt++)
            #pragma unroll
            for (int r = 0; r < 4; r++) d[mt][nt][r] = 0.f;

    const uint4* xb4 = (const uint4*)g_xb;   // 128 uint4 per row
    const uint4* wb4 = (const uint4*)g_wb;

    const int xr0 = tid >> 2;
    const int xr1 = (tid + 256) >> 2;
    const int xq  = tid & 3;

    // prologue: stages 0 and 1
    #pragma unroll
    for (int p = 0; p < 2; p++) {
        const int kq = p * 4;
        cp_async16(&Xs[p][xr0][xq * 4], &xb4[(size_t)(bm + xr0) * 128 + kq + xq]);
        cp_async16(&Xs[p][xr1][xq * 4], &xb4[(size_t)(bm + xr1) * 128 + kq + xq]);
        cp_async16(&Ws[p][xr0][xq * 4], &wb4[(size_t)(bn + xr0) * 128 + kq + xq]);
        asm volatile("cp.async.commit_group;");
    }

    for (int it = 0; it < R_NI; it++) {
        const int s = it % NSTAGE;
        if (it == R_NI - 1) asm volatile("cp.async.wait_group 0;");
        else                asm volatile("cp.async.wait_group 1;");
        __syncthreads();
        if (it + 2 < R_NI) {
            const int s2 = (it + 2) % NSTAGE;
            const int kq = (it + 2) * 4;
            cp_async16(&Xs[s2][xr0][xq * 4], &xb4[(size_t)(bm + xr0) * 128 + kq + xq]);
            cp_async16(&Xs[s2][xr1][xq * 4], &xb4[(size_t)(bm + xr1) * 128 + kq + xq]);
            cp_async16(&Ws[s2][xr0][xq * 4], &wb4[(size_t)(bn + xr0) * 128 + kq + xq]);
            asm volatile("cp.async.commit_group;");
        }

        #pragma unroll
        for (int ks = 0; ks < 2; ks++) {
            const int kw = ks * 8 + t;
            unsigned a[2][4];
            #pragma unroll
            for (int mt = 0; mt < 2; mt++) {
                const int rb = wm * 32 + mt * 16;
                a[mt][0] = Xs[s][rb + g    ][kw];
                a[mt][1] = Xs[s][rb + g + 8][kw];
                a[mt][2] = Xs[s][rb + g    ][kw + 4];
                a[mt][3] = Xs[s][rb + g + 8][kw + 4];
            }
            unsigned b[4][2];
            #pragma unroll
            for (int nt = 0; nt < 4; nt++) {
                const int cb = wn * 32 + nt * 8;
                b[nt][0] = Ws[s][cb + g][kw];
                b[nt][1] = Ws[s][cb + g][kw + 4];
            }
            #pragma unroll
            for (int mt = 0; mt < 2; mt++)
                #pragma unroll
                for (int nt = 0; nt < 4; nt++)
                    mma_bf16(d[mt][nt], a[mt], b[nt]);
        }
    }

    #pragma unroll
    for (int mt = 0; mt < 2; mt++) {
        #pragma unroll
        for (int nt = 0; nt < 4; nt++) {
            const int row = bm + wm * 32 + mt * 16 + g;
            const int col = bn + wn * 32 + nt * 8 + 2 * t;
            *(float2*)(g_logits + (size_t)row * E + col)       = make_float2(d[mt][nt][0], d[mt][nt][1]);
            *(float2*)(g_logits + (size_t)(row + 8) * E + col) = make_float2(d[mt][nt][2], d[mt][nt][3]);
        }
    }
}

// ============== Kernel 2a: routing (top-4 + exact rerank + softmax) ========
#define NCAND 4

__global__ __launch_bounds__(256)
void route_kernel(const float* __restrict__ x,
                  const float* __restrict__ RW,
                  int M, int E) {
    const int wid  = threadIdx.x >> 5;
    const int lane = threadIdx.x & 31;
    const int n    = blockIdx.x * 8 + wid;
    if (n >= M) return;

    // logits for this token
    const int NJ = E >> 5;
    float lv[8];
    const float* lrow = g_logits + (size_t)n * E;
    #pragma unroll
    for (int j = 0; j < 8; j++) lv[j] = (j < NJ) ? lrow[lane + 32 * j] : -3.4e38f;

    // x row chunk in regs (coalesced)
    float4 xr4[8];
    const float4* xg = (const float4*)(x + (size_t)n * 1024);
    #pragma unroll
    for (int q = 0; q < 8; q++) xr4[q] = xg[q * 32 + lane];

    int cand[NCAND];
    #pragma unroll
    for (int it = 0; it < NCAND; it++) {
        float bv = -3.4e38f; int be = 0x7fffffff;
        #pragma unroll
        for (int j = 0; j < 8; j++) {
            int e = lane + 32 * j;
            if (j < NJ && pair_better(lv[j], e, bv, be)) { bv = lv[j]; be = e; }
        }
        #pragma unroll
        for (int off = 16; off > 0; off >>= 1) {
            float ov = __shfl_xor_sync(0xffffffffu, bv, off);
            int   oe = __shfl_xor_sync(0xffffffffu, be, off);
            if (pair_better(ov, oe, bv, be)) { bv = ov; be = oe; }
        }
        cand[it] = be;
        if ((be & 31) == lane) lv[be >> 5] = -3.4e38f;
    }

    float s[NCAND];
    #pragma unroll
    for (int c = 0; c < NCAND; c++) {
        const float4* wr = (const float4*)(RW + (size_t)cand[c] * 1024);
        float acc = 0.f;
        #pragma unroll
        for (int q = 0; q < 8; q++) {
            float4 wv = wr[q * 32 + lane];
            acc += xr4[q].x * wv.x + xr4[q].y * wv.y + xr4[q].z * wv.z + xr4[q].w * wv.w;
        }
        s[c] = acc;
    }
    #pragma unroll
    for (int off = 16; off > 0; off >>= 1) {
        #pragma unroll
        for (int c = 0; c < NCAND; c++) s[c] += __shfl_xor_sync(0xffffffffu, s[c], off);
    }

    float v0 = s[0]; int c0 = 0;
    #pragma unroll
    for (int c = 1; c < NCAND; c++)
        if (pair_better(s[c], cand[c], v0, cand[c0])) { v0 = s[c]; c0 = c; }
    float v1 = -3.4e38f; int c1 = -1;
    #pragma unroll
    for (int c = 0; c < NCAND; c++)
        if (c != c0 && (c1 < 0 || pair_better(s[c], cand[c], v1, cand[c1]))) { v1 = s[c]; c1 = c; }

    if (lane == 0) {
        const float tt = expf(v1 - v0);
        const float w0 = 1.f / (1.f + tt);
        g_eidx[n] = make_int2(cand[c0], cand[c1]);
        g_gate[n] = make_float2(w0, tt * w0);
    }
}

// ============== Kernel 2b: tensor-core expert compute ================
#define TPB_TOK 4
#define XSTRIDE 36
#define YSTRIDE 34

__global__ __launch_bounds__(128, 4)
void expert_kernel(const float* __restrict__ x,
                   const float* __restrict__ scale,
                   const float* __restrict__ bias,
                   float* __restrict__ out, int M) {
    __shared__ float XsAll[TPB_TOK][32 * XSTRIDE];
    const int wid  = threadIdx.x >> 5;
    const int lane = threadIdx.x & 31;
    const int n    = blockIdx.x * TPB_TOK + wid;
    if (n >= M) return;
    float* xs = XsAll[wid];
    const int g = lane >> 2;
    const int t = lane & 3;

    // route (broadcast loads) — available immediately
    const int2   ee = g_eidx[n];
    const float2 ww = g_gate[n];
    const int e0 = ee.x, e1 = ee.y;
    const float w0 = ww.x, w1 = ww.y;

    // x row into smem
    {
        const float4* xg = (const float4*)(x + (size_t)n * 1024);
        #pragma unroll
        for (int i = 0; i < 8; i++) {
            int idx = i * 32 + lane;
            int r   = idx >> 3;
            int q   = idx & 7;
            float4 v = xg[idx];
            *(float4*)&xs[r * XSTRIDE + q * 4] = v;
        }
    }
    __syncwarp();

    // X b-fragments (bf16 hi/lo)
    unsigned xbh[2][4][2], xbl[2][4][2];
    #pragma unroll
    for (int kt = 0; kt < 2; kt++)
        #pragma unroll
        for (int nt = 0; nt < 4; nt++)
            #pragma unroll
            for (int part = 0; part < 2; part++) {
                int krow = kt * 16 + 2 * t + 8 * part;
                float e0f = xs[krow * XSTRIDE + nt * 8 + g];
                float e1f = xs[(krow + 1) * XSTRIDE + nt * 8 + g];
                split_pair(e0f, e1f, xbh[kt][nt][part], xbl[kt][nt][part]);
            }

    float Y[2][4][4];
    #pragma unroll
    for (int mt = 0; mt < 2; mt++)
        #pragma unroll
        for (int nt = 0; nt < 4; nt++)
            #pragma unroll
            for (int r = 0; r < 4; r++) Y[mt][nt][r] = 0.f;

    #pragma unroll
    for (int kk = 0; kk < 2; kk++) {
        const int   e = kk ? e1 : e0;
        const float w = kk ? w1 : w0;

        float tA[2][4][4];
        #pragma unroll
        for (int mt = 0; mt < 2; mt++)
            #pragma unroll
            for (int nt = 0; nt < 4; nt++)
                #pragma unroll
                for (int r = 0; r < 4; r++) tA[mt][nt][r] = 0.f;

        #pragma unroll
        for (int kt = 0; kt < 2; kt++) {
            #pragma unroll
            for (int mt = 0; mt < 2; mt++) {
                int off = (((e * 2 + kt) * 2) + mt) * 32 + lane;
                uint4 ah4 = g_Ah[off];
                uint4 al4 = g_Al[off];
                unsigned ah[4] = {ah4.x, ah4.y, ah4.z, ah4.w};
                unsigned al[4] = {al4.x, al4.y, al4.z, al4.w};
                #pragma unroll
                for (int nt = 0; nt < 4; nt++) {
                    mma_bf16(tA[mt][nt], ah, xbh[kt][nt]);
                    mma_bf16(tA[mt][nt], ah, xbl[kt][nt]);
                    mma_bf16(tA[mt][nt], al, xbh[kt][nt]);
                }
            }
        }

        unsigned th[2][2][4], tl[2][2][4];
        #pragma unroll
        for (int mt = 0; mt < 2; mt++)
            #pragma unroll
            for (int ktB = 0; ktB < 2; ktB++) {
                float c00 = w * tA[mt][2 * ktB][0],     c01 = w * tA[mt][2 * ktB][1];
                float c02 = w * tA[mt][2 * ktB][2],     c03 = w * tA[mt][2 * ktB][3];
                float c10 = w * tA[mt][2 * ktB + 1][0], c11 = w * tA[mt][2 * ktB + 1][1];
                float c12 = w * tA[mt][2 * ktB + 1][2], c13 = w * tA[mt][2 * ktB + 1][3];
                split_pair(c00, c01, th[mt][ktB][0], tl[mt][ktB][0]);
                split_pair(c02, c03, th[mt][ktB][1], tl[mt][ktB][1]);
                split_pair(c10, c11, th[mt][ktB][2], tl[mt][ktB][2]);
                split_pair(c12, c13, th[mt][ktB][3], tl[mt][ktB][3]);
            }

        #pragma unroll
        for (int kt = 0; kt < 2; kt++)
            #pragma unroll
            for (int nt = 0; nt < 4; nt++) {
                int off = (((e * 2 + kt) * 4) + nt) * 32 + lane;
                uint2 bh2 = g_Bh[off];
                uint2 bl2 = g_Bl[off];
                unsigned bh[2] = {bh2.x, bh2.y};
                unsigned bl[2] = {bl2.x, bl2.y};
                #pragma unroll
                for (int mt = 0; mt < 2; mt++) {
                    mma_bf16(Y[mt][nt], th[mt][kt], bh);
                    mma_bf16(Y[mt][nt], th[mt][kt], bl);
                    mma_bf16(Y[mt][nt], tl[mt][kt], bh);
                }
            }
    }

    __syncwarp();
    #pragma unroll
    for (int mt = 0; mt < 2; mt++)
        #pragma unroll
        for (int nt = 0; nt < 4; nt++) {
            int o0 = mt * 16 + g, p0 = nt * 8 + 2 * t;
            *(float2*)&xs[o0 * YSTRIDE + p0]       = make_float2(Y[mt][nt][0], Y[mt][nt][1]);
            *(float2*)&xs[(o0 + 8) * YSTRIDE + p0] = make_float2(Y[mt][nt][2], Y[mt][nt][3]);
        }
    __syncwarp();
    const float sc = *scale;
    float* og = out + (size_t)n * 1024;
    #pragma unroll
    for (int i = 0; i < 32; i++) {
        int q = i * 32 + lane;
        og[q] = xs[i * YSTRIDE + lane] * sc + bias[q];
    }
}

// ================================ launch ===================================
extern "C" void kernel_launch(void* const* d_in, const int* in_sizes, int n_in,
                              void* d_out, int out_size) {
    const float* x  = (const float*)d_in[0];
    const float* rw = (const float*)d_in[1];
    const float* Ae = (const float*)d_in[2];
    const float* Be = (const float*)d_in[3];
    const float* sc = (const float*)d_in[4];
    const float* bi = (const float*)d_in[5];
    float* out = (float*)d_out;

    const int M = in_sizes[0] / ROUTER_K;   // 16384
    const int E = in_sizes[1] / ROUTER_K;   // 256

    const int nx8 = (M * ROUTER_K) / 8;
    const int nw8 = (E * ROUTER_K) / 8;
    const int nfrag = E * 32;
    convert_kernel<<<(nx8 + nw8 + nfrag + 255) / 256, 256>>>(x, rw, Ae, Be, nx8, nw8, E);

    dim3 g1(M / R_BM, E / R_BN);
    router_mma_kernel<<<g1, 256>>>(M, E);

    route_kernel<<<(M + 7) / 8, 256>>>(x, rw, M, E);

    expert_kernel<<<(M + TPB_TOK - 1) / TPB_TOK, 128>>>(x, sc, bi, out, M);
}

// round 9
// speedup vs baseline: 2.5055x; 1.0416x over previous
#include <cuda_runtime.h>
#include <cuda_bf16.h>
#include <math.h>

// ---------------------------------------------------------------------------
// KroneckerMoE v9:
//   K0: preconvert X,W fp32->bf16 + pre-split A,B mma fragments
//   K1: router logits (bf16 OUT), bf16 mma.sync, BN=128 single-wave,
//       2-stage cp.async
//   K2a: routing: approx top-4 (bf16 logits) -> exact fp32 rerank -> softmax
//        (scale folded into gates) -> route table
//   K2b: expert compute: tensor-core bilinear (3-term bf16 split)
// ---------------------------------------------------------------------------

#define ROUTER_K   1024
#define MAX_TOKENS 16384
#define MAX_E      256

__device__ unsigned g_lb[(size_t)MAX_TOKENS * MAX_E / 2];        // logits bf16x2
__device__ unsigned g_xb[(size_t)MAX_TOKENS * (ROUTER_K / 2)];   // bf16x2
__device__ unsigned g_wb[(size_t)MAX_E * (ROUTER_K / 2)];        // bf16x2
__device__ uint4 g_Ah[MAX_E * 2 * 2 * 32];
__device__ uint4 g_Al[MAX_E * 2 * 2 * 32];
__device__ uint2 g_Bh[MAX_E * 2 * 4 * 32];
__device__ uint2 g_Bl[MAX_E * 2 * 4 * 32];
__device__ int2   g_eidx[MAX_TOKENS];
__device__ float2 g_gate[MAX_TOKENS];

// ======================= helpers =========================
__device__ __forceinline__ void mma_bf16(float d[4], const unsigned a[4], const unsigned b[2]) {
    asm volatile(
        "mma.sync.aligned.m16n8k16.row.col.f32.bf16.bf16.f32 "
        "{%0,%1,%2,%3}, {%4,%5,%6,%7}, {%8,%9}, {%0,%1,%2,%3};\n"
        : "+f"(d[0]), "+f"(d[1]), "+f"(d[2]), "+f"(d[3])
        : "r"(a[0]), "r"(a[1]), "r"(a[2]), "r"(a[3]), "r"(b[0]), "r"(b[1]));
}
__device__ __forceinline__ unsigned cvt2_bf16(float hi, float lo) {
    unsigned d;
    asm("cvt.rn.bf16x2.f32 %0, %1, %2;" : "=r"(d) : "f"(hi), "f"(lo));
    return d;
}
__device__ __forceinline__ float bf16lo_f(unsigned u) { return __uint_as_float(u << 16); }
__device__ __forceinline__ float bf16hi_f(unsigned u) { return __uint_as_float(u & 0xffff0000u); }
__device__ __forceinline__ void split_pair(float e0, float e1, unsigned& h, unsigned& l) {
    h = cvt2_bf16(e1, e0);
    float r0 = e0 - bf16lo_f(h);
    float r1 = e1 - bf16hi_f(h);
    l = cvt2_bf16(r1, r0);
}
__device__ __forceinline__ bool pair_better(float v, int i, float w, int j) {
    return (v > w) || (v == w && i < j);
}
__device__ __forceinline__ void cp_async16(void* smem, const void* gmem) {
    unsigned s = (unsigned)__cvta_generic_to_shared(smem);
    asm volatile("cp.async.cg.shared.global [%0], [%1], 16;" :: "r"(s), "l"(gmem));
}

// ========= Kernel 0: X,W bf16 convert + A,B frag split ========
__global__ __launch_bounds__(256)
void convert_kernel(const float* __restrict__ X, const float* __restrict__ W,
                    const float* __restrict__ Ae, const float* __restrict__ Be,
                    int nx8, int nw8, int E) {
    int i = blockIdx.x * blockDim.x + threadIdx.x;
    if (i < nx8) {
        float4 v0 = ((const float4*)X)[2 * (size_t)i];
        float4 v1 = ((const float4*)X)[2 * (size_t)i + 1];
        uint4 u = make_uint4(cvt2_bf16(v0.y, v0.x), cvt2_bf16(v0.w, v0.z),
                             cvt2_bf16(v1.y, v1.x), cvt2_bf16(v1.w, v1.z));
        ((uint4*)g_xb)[i] = u;
    } else if (i < nx8 + nw8) {
        int j = i - nx8;
        float4 v0 = ((const float4*)W)[2 * (size_t)j];
        float4 v1 = ((const float4*)W)[2 * (size_t)j + 1];
        uint4 u = make_uint4(cvt2_bf16(v0.y, v0.x), cvt2_bf16(v0.w, v0.z),
                             cvt2_bf16(v1.y, v1.x), cvt2_bf16(v1.w, v1.z));
        ((uint4*)g_wb)[j] = u;
    } else {
        int j = i - nx8 - nw8;
        int e = j >> 5;
        if (e >= E) return;
        int lane = j & 31;
        int g = lane >> 2, t = lane & 3;
        #pragma unroll
        for (int kt = 0; kt < 2; kt++)
            #pragma unroll
            for (int mt = 0; mt < 2; mt++) {
                const float* ap = Ae + (size_t)e * 1024 + (mt * 16 + g) * 32 + kt * 16;
                float2 p0 = *(const float2*)(ap + 2 * t);
                float2 p1 = *(const float2*)(ap + 2 * t + 8);
                float2 p2 = *(const float2*)(ap + 8 * 32 + 2 * t);
                float2 p3 = *(const float2*)(ap + 8 * 32 + 2 * t + 8);
                uint4 h, l;
                split_pair(p0.x, p0.y, h.x, l.x);
                split_pair(p2.x, p2.y, h.y, l.y);
                split_pair(p1.x, p1.y, h.z, l.z);
                split_pair(p3.x, p3.y, h.w, l.w);
                int off = (((e * 2 + kt) * 2) + mt) * 32 + lane;
                g_Ah[off] = h;
                g_Al[off] = l;
            }
        #pragma unroll
        for (int kt = 0; kt < 2; kt++)
            #pragma unroll
            for (int nt = 0; nt < 4; nt++) {
                const float* bp = Be + (size_t)e * 1024 + (nt * 8 + g) * 32 + kt * 16;
                float2 q0 = *(const float2*)(bp + 2 * t);
                float2 q1 = *(const float2*)(bp + 2 * t + 8);
                uint2 h, l;
                split_pair(q0.x, q0.y, h.x, l.x);
                split_pair(q1.x, q1.y, h.y, l.y);
                int off = (((e * 2 + kt) * 4) + nt) * 32 + lane;
                g_Bh[off] = h;
                g_Bl[off] = l;
            }
    }
}

// ===== Kernel 1: bf16 mma router, BN=128, 2-stage cp.async, bf16 out ======
#define R_BM 128
#define R_BN 128
#define R_BK 32
#define XPAD 20
#define R_NI (ROUTER_K / R_BK)   // 32

__global__ __launch_bounds__(256)
void router_mma_kernel(int M, int E) {
    __shared__ unsigned Xs[2][R_BM][XPAD];
    __shared__ unsigned Ws[2][R_BN][XPAD];
    const int bm   = blockIdx.x * R_BM;
    const int bn   = blockIdx.y * R_BN;
    const int tid  = threadIdx.x;
    const int wid  = tid >> 5;
    const int lane = tid & 31;
    const int wm   = wid & 3;      // 4 warps along M (32 rows each)
    const int wn   = wid >> 2;     // 2 warps along N (64 cols each)
    const int g    = lane >> 2;
    const int t    = lane & 3;

    float d[2][8][4];
    #pragma unroll
    for (int mt = 0; mt < 2; mt++)
        #pragma unroll
        for (int nt = 0; nt < 8; nt++)
            #pragma unroll
            for (int r = 0; r < 4; r++) d[mt][nt][r] = 0.f;

    const uint4* xb4 = (const uint4*)g_xb;   // 128 uint4 per row
    const uint4* wb4 = (const uint4*)g_wb;

    const int r0 = tid >> 2;            // 0..63
    const int r1 = r0 + 64;             // 64..127
    const int q  = tid & 3;

    // prologue: stage 0
    {
        cp_async16(&Xs[0][r0][q * 4], &xb4[(size_t)(bm + r0) * 128 + q]);
        cp_async16(&Xs[0][r1][q * 4], &xb4[(size_t)(bm + r1) * 128 + q]);
        cp_async16(&Ws[0][r0][q * 4], &wb4[(size_t)(bn + r0) * 128 + q]);
        cp_async16(&Ws[0][r1][q * 4], &wb4[(size_t)(bn + r1) * 128 + q]);
        asm volatile("cp.async.commit_group;");
    }

    for (int it = 0; it < R_NI; it++) {
        const int s = it & 1;
        if (it + 1 < R_NI) {
            const int s1 = s ^ 1;
            const int kq = (it + 1) * 4;
            cp_async16(&Xs[s1][r0][q * 4], &xb4[(size_t)(bm + r0) * 128 + kq + q]);
            cp_async16(&Xs[s1][r1][q * 4], &xb4[(size_t)(bm + r1) * 128 + kq + q]);
            cp_async16(&Ws[s1][r0][q * 4], &wb4[(size_t)(bn + r0) * 128 + kq + q]);
            cp_async16(&Ws[s1][r1][q * 4], &wb4[(size_t)(bn + r1) * 128 + kq + q]);
            asm volatile("cp.async.commit_group;");
            asm volatile("cp.async.wait_group 1;");
        } else {
            asm volatile("cp.async.wait_group 0;");
        }
        __syncthreads();

        #pragma unroll
        for (int ks = 0; ks < 2; ks++) {
            const int kw = ks * 8 + t;
            unsigned a[2][4];
            #pragma unroll
            for (int mt = 0; mt < 2; mt++) {
                const int rb = wm * 32 + mt * 16;
                a[mt][0] = Xs[s][rb + g    ][kw];
                a[mt][1] = Xs[s][rb + g + 8][kw];
                a[mt][2] = Xs[s][rb + g    ][kw + 4];
                a[mt][3] = Xs[s][rb + g + 8][kw + 4];
            }
            unsigned b[8][2];
            #pragma unroll
            for (int nt = 0; nt < 8; nt++) {
                const int cb = wn * 64 + nt * 8;
                b[nt][0] = Ws[s][cb + g][kw];
                b[nt][1] = Ws[s][cb + g][kw + 4];
            }
            #pragma unroll
            for (int mt = 0; mt < 2; mt++)
                #pragma unroll
                for (int nt = 0; nt < 8; nt++)
                    mma_bf16(d[mt][nt], a[mt], b[nt]);
        }
        __syncthreads();
    }

    // epilogue: store logits as bf16x2 words
    const int E2 = E >> 1;
    #pragma unroll
    for (int mt = 0; mt < 2; mt++) {
        #pragma unroll
        for (int nt = 0; nt < 8; nt++) {
            const int row = bm + wm * 32 + mt * 16 + g;
            const int cw  = (bn + wn * 64 + nt * 8) / 2 + t;   // word index
            g_lb[(size_t)row * E2 + cw]       = cvt2_bf16(d[mt][nt][1], d[mt][nt][0]);
            g_lb[(size_t)(row + 8) * E2 + cw] = cvt2_bf16(d[mt][nt][3], d[mt][nt][2]);
        }
    }
}

// ============== Kernel 2a: routing (top-4 + exact rerank + softmax) ========
#define NCAND 4

__global__ __launch_bounds__(256)
void route_kernel(const float* __restrict__ x,
                  const float* __restrict__ RW,
                  const float* __restrict__ scale,
                  int M, int E) {
    const int wid  = threadIdx.x >> 5;
    const int lane = threadIdx.x & 31;
    const int n    = blockIdx.x * 8 + wid;
    if (n >= M) return;

    // bf16 logits for this token
    const int NJ = E >> 5;
    float lv[8];
    const __nv_bfloat16* lrow = (const __nv_bfloat16*)g_lb + (size_t)n * E;
    #pragma unroll
    for (int j = 0; j < 8; j++)
        lv[j] = (j < NJ) ? __bfloat162float(lrow[lane + 32 * j]) : -3.4e38f;

    // x row chunk in regs (coalesced)
    float4 xr4[8];
    const float4* xg = (const float4*)(x + (size_t)n * 1024);
    #pragma unroll
    for (int q = 0; q < 8; q++) xr4[q] = xg[q * 32 + lane];

    int cand[NCAND];
    #pragma unroll
    for (int it = 0; it < NCAND; it++) {
        float bv = -3.4e38f; int be = 0x7fffffff;
        #pragma unroll
        for (int j = 0; j < 8; j++) {
            int e = lane + 32 * j;
            if (j < NJ && pair_better(lv[j], e, bv, be)) { bv = lv[j]; be = e; }
        }
        #pragma unroll
        for (int off = 16; off > 0; off >>= 1) {
            float ov = __shfl_xor_sync(0xffffffffu, bv, off);
            int   oe = __shfl_xor_sync(0xffffffffu, be, off);
            if (pair_better(ov, oe, bv, be)) { bv = ov; be = oe; }
        }
        cand[it] = be;
        if ((be & 31) == lane) lv[be >> 5] = -3.4e38f;
    }

    float s[NCAND];
    #pragma unroll
    for (int c = 0; c < NCAND; c++) {
        const float4* wr = (const float4*)(RW + (size_t)cand[c] * 1024);
        float acc = 0.f;
        #pragma unroll
        for (int q = 0; q < 8; q++) {
            float4 wv = wr[q * 32 + lane];
            acc += xr4[q].x * wv.x + xr4[q].y * wv.y + xr4[q].z * wv.z + xr4[q].w * wv.w;
        }
        s[c] = acc;
    }
    #pragma unroll
    for (int off = 16; off > 0; off >>= 1) {
        #pragma unroll
        for (int c = 0; c < NCAND; c++) s[c] += __shfl_xor_sync(0xffffffffu, s[c], off);
    }

    float v0 = s[0]; int c0 = 0;
    #pragma unroll
    for (int c = 1; c < NCAND; c++)
        if (pair_better(s[c], cand[c], v0, cand[c0])) { v0 = s[c]; c0 = c; }
    float v1 = -3.4e38f; int c1 = -1;
    #pragma unroll
    for (int c = 0; c < NCAND; c++)
        if (c != c0 && (c1 < 0 || pair_better(s[c], cand[c], v1, cand[c1]))) { v1 = s[c]; c1 = c; }

    if (lane == 0) {
        const float sc = *scale;                 // fold output scale into gates
        const float tt = expf(v1 - v0);
        const float w0 = 1.f / (1.f + tt);
        g_eidx[n] = make_int2(cand[c0], cand[c1]);
        g_gate[n] = make_float2(w0 * sc, tt * w0 * sc);
    }
}

// ============== Kernel 2b: tensor-core expert compute ================
#define TPB_TOK 4
#define XSTRIDE 36
#define YSTRIDE 34

__global__ __launch_bounds__(128, 4)
void expert_kernel(const float* __restrict__ x,
                   const float* __restrict__ bias,
                   float* __restrict__ out, int M) {
    __shared__ float XsAll[TPB_TOK][32 * XSTRIDE];
    const int wid  = threadIdx.x >> 5;
    const int lane = threadIdx.x & 31;
    const int n    = blockIdx.x * TPB_TOK + wid;
    if (n >= M) return;
    float* xs = XsAll[wid];
    const int g = lane >> 2;
    const int t = lane & 3;

    const int2   ee = g_eidx[n];
    const float2 ww = g_gate[n];
    const int e0 = ee.x, e1 = ee.y;
    const float w0 = ww.x, w1 = ww.y;

    {
        const float4* xg = (const float4*)(x + (size_t)n * 1024);
        #pragma unroll
        for (int i = 0; i < 8; i++) {
            int idx = i * 32 + lane;
            int r   = idx >> 3;
            int q   = idx & 7;
            float4 v = xg[idx];
            *(float4*)&xs[r * XSTRIDE + q * 4] = v;
        }
    }
    __syncwarp();

    unsigned xbh[2][4][2], xbl[2][4][2];
    #pragma unroll
    for (int kt = 0; kt < 2; kt++)
        #pragma unroll
        for (int nt = 0; nt < 4; nt++)
            #pragma unroll
            for (int part = 0; part < 2; part++) {
                int krow = kt * 16 + 2 * t + 8 * part;
                float e0f = xs[krow * XSTRIDE + nt * 8 + g];
                float e1f = xs[(krow + 1) * XSTRIDE + nt * 8 + g];
                split_pair(e0f, e1f, xbh[kt][nt][part], xbl[kt][nt][part]);
            }

    float Y[2][4][4];
    #pragma unroll
    for (int mt = 0; mt < 2; mt++)
        #pragma unroll
        for (int nt = 0; nt < 4; nt++)
            #pragma unroll
            for (int r = 0; r < 4; r++) Y[mt][nt][r] = 0.f;

    #pragma unroll
    for (int kk = 0; kk < 2; kk++) {
        const int   e = kk ? e1 : e0;
        const float w = kk ? w1 : w0;

        float tA[2][4][4];
        #pragma unroll
        for (int mt = 0; mt < 2; mt++)
            #pragma unroll
            for (int nt = 0; nt < 4; nt++)
                #pragma unroll
                for (int r = 0; r < 4; r++) tA[mt][nt][r] = 0.f;

        #pragma unroll
        for (int kt = 0; kt < 2; kt++) {
            #pragma unroll
            for (int mt = 0; mt < 2; mt++) {
                int off = (((e * 2 + kt) * 2) + mt) * 32 + lane;
                uint4 ah4 = g_Ah[off];
                uint4 al4 = g_Al[off];
                unsigned ah[4] = {ah4.x, ah4.y, ah4.z, ah4.w};
                unsigned al[4] = {al4.x, al4.y, al4.z, al4.w};
                #pragma unroll
                for (int nt = 0; nt < 4; nt++) {
                    mma_bf16(tA[mt][nt], ah, xbh[kt][nt]);
                    mma_bf16(tA[mt][nt], ah, xbl[kt][nt]);
                    mma_bf16(tA[mt][nt], al, xbh[kt][nt]);
                }
            }
        }

        unsigned th[2][2][4], tl[2][2][4];
        #pragma unroll
        for (int mt = 0; mt < 2; mt++)
            #pragma unroll
            for (int ktB = 0; ktB < 2; ktB++) {
                float c00 = w * tA[mt][2 * ktB][0],     c01 = w * tA[mt][2 * ktB][1];
                float c02 = w * tA[mt][2 * ktB][2],     c03 = w * tA[mt][2 * ktB][3];
                float c10 = w * tA[mt][2 * ktB + 1][0], c11 = w * tA[mt][2 * ktB + 1][1];
                float c12 = w * tA[mt][2 * ktB + 1][2], c13 = w * tA[mt][2 * ktB + 1][3];
                split_pair(c00, c01, th[mt][ktB][0], tl[mt][ktB][0]);
                split_pair(c02, c03, th[mt][ktB][1], tl[mt][ktB][1]);
                split_pair(c10, c11, th[mt][ktB][2], tl[mt][ktB][2]);
                split_pair(c12, c13, th[mt][ktB][3], tl[mt][ktB][3]);
            }

        #pragma unroll
        for (int kt = 0; kt < 2; kt++)
            #pragma unroll
            for (int nt = 0; nt < 4; nt++) {
                int off = (((e * 2 + kt) * 4) + nt) * 32 + lane;
                uint2 bh2 = g_Bh[off];
                uint2 bl2 = g_Bl[off];
                unsigned bh[2] = {bh2.x, bh2.y};
                unsigned bl[2] = {bl2.x, bl2.y};
                #pragma unroll
                for (int mt = 0; mt < 2; mt++) {
                    mma_bf16(Y[mt][nt], th[mt][kt], bh);
                    mma_bf16(Y[mt][nt], th[mt][kt], bl);
                    mma_bf16(Y[mt][nt], tl[mt][kt], bh);
                }
            }
    }

    __syncwarp();
    #pragma unroll
    for (int mt = 0; mt < 2; mt++)
        #pragma unroll
        for (int nt = 0; nt < 4; nt++) {
            int o0 = mt * 16 + g, p0 = nt * 8 + 2 * t;
            *(float2*)&xs[o0 * YSTRIDE + p0]       = make_float2(Y[mt][nt][0], Y[mt][nt][1]);
            *(float2*)&xs[(o0 + 8) * YSTRIDE + p0] = make_float2(Y[mt][nt][2], Y[mt][nt][3]);
        }
    __syncwarp();
    float* og = out + (size_t)n * 1024;
    #pragma unroll
    for (int i = 0; i < 32; i++) {
        int q = i * 32 + lane;
        og[q] = xs[i * YSTRIDE + lane] + bias[q];
    }
}

// ================================ launch ===================================
extern "C" void kernel_launch(void* const* d_in, const int* in_sizes, int n_in,
                              void* d_out, int out_size) {
    const float* x  = (const float*)d_in[0];
    const float* rw = (const float*)d_in[1];
    const float* Ae = (const float*)d_in[2];
    const float* Be = (const float*)d_in[3];
    const float* sc = (const float*)d_in[4];
    const float* bi = (const float*)d_in[5];
    float* out = (float*)d_out;

    const int M = in_sizes[0] / ROUTER_K;   // 16384
    const int E = in_sizes[1] / ROUTER_K;   // 256

    const int nx8 = (M * ROUTER_K) / 8;
    const int nw8 = (E * ROUTER_K) / 8;
    const int nfrag = E * 32;
    convert_kernel<<<(nx8 + nw8 + nfrag + 255) / 256, 256>>>(x, rw, Ae, Be, nx8, nw8, E);

    dim3 g1(M / R_BM, E / R_BN);
    router_mma_kernel<<<g1, 256>>>(M, E);

    route_kernel<<<(M + 7) / 8, 256>>>(x, rw, sc, M, E);

    expert_kernel<<<(M + TPB_TOK - 1) / TPB_TOK, 128>>>(x, bi, out, M);
}